// round 14
// baseline (speedup 1.0000x reference)
#include <cuda_runtime.h>
#include <cuda_bf16.h>
#include <math.h>
#include <stdint.h>

// Problem constants
#define Bb   8
#define Ss   1024
#define Ee   512
#define Hh   8
#define DHd  64
#define Mm   (Bb * Ss)        // 8192
#define QKVN (3 * Ee)         // 1536
#define LOCALW 3

// ---------------- scratch (device globals) ----------------------------------
__device__ float g_qkv_l[(size_t)Mm * QKVN];
__device__ float g_vg   [(size_t)Mm * Ee];
__device__ float g_Wc   [(size_t)Ee * 2 * Ee];
__device__ float g_bc   [Ee];
__device__ __nv_bfloat16 g_A1h[(size_t)Mm * Ee];
__device__ __nv_bfloat16 g_A1l[(size_t)Mm * Ee];
__device__ __nv_bfloat16 g_B1lh[(size_t)QKVN * Ee];
__device__ __nv_bfloat16 g_B1ll[(size_t)QKVN * Ee];
__device__ __nv_bfloat16 g_B1gh[(size_t)QKVN * Ee];
__device__ __nv_bfloat16 g_B1gl[(size_t)QKVN * Ee];
__device__ __nv_bfloat16 g_A2h[(size_t)Mm * 1024];
__device__ __nv_bfloat16 g_A2l[(size_t)Mm * 1024];
__device__ __nv_bfloat16 g_B2h[(size_t)Ee * 1024];
__device__ __nv_bfloat16 g_B2l[(size_t)Ee * 1024];
__device__ __nv_bfloat16 g_qk_h[(size_t)Mm * 1024];
__device__ __nv_bfloat16 g_qk_l[(size_t)Mm * 1024];
__device__ __nv_bfloat16 g_vt_h[(size_t)64 * 64 * Ss];
__device__ __nv_bfloat16 g_vt_l[(size_t)64 * 64 * Ss];

// ---------------- PTX helpers (base ISA only) --------------------------------
__device__ __forceinline__ uint32_t smem_u32(const void* p) {
    uint32_t a;
    asm("{ .reg .u64 t; cvta.to.shared.u64 t, %1; cvt.u32.u64 %0, t; }"
        : "=r"(a) : "l"(p));
    return a;
}
__device__ __forceinline__ uint32_t sw128(uint32_t o) { return o ^ ((o >> 3) & 0x70); }
__device__ __forceinline__ uint32_t sw64(uint32_t o)  { return o ^ ((o >> 3) & 0x30); }

__device__ __forceinline__ void cp16(uint32_t dst, const void* src) {
    asm volatile("cp.async.cg.shared.global [%0], [%1], 16;"
                 :: "r"(dst), "l"(src) : "memory");
}
__device__ __forceinline__ void ldsm4(uint32_t* d, uint32_t a) {
    asm volatile("ldmatrix.sync.aligned.m8n8.x4.shared.b16 {%0,%1,%2,%3}, [%4];"
                 : "=r"(d[0]), "=r"(d[1]), "=r"(d[2]), "=r"(d[3]) : "r"(a));
}
__device__ __forceinline__ void mma16816(float* c, const uint32_t* a,
                                         uint32_t b0, uint32_t b1) {
    asm volatile("mma.sync.aligned.m16n8k16.row.col.f32.bf16.bf16.f32 "
                 "{%0,%1,%2,%3}, {%4,%5,%6,%7}, {%8,%9}, {%0,%1,%2,%3};"
                 : "+f"(c[0]), "+f"(c[1]), "+f"(c[2]), "+f"(c[3])
                 : "r"(a[0]), "r"(a[1]), "r"(a[2]), "r"(a[3]), "r"(b0), "r"(b1));
}
__device__ __forceinline__ uint32_t pack_bf2(float a, float b, float& ra, float& rb) {
    __nv_bfloat16 ha = __float2bfloat16(a), hb = __float2bfloat16(b);
    ra = a - __bfloat162float(ha);
    rb = b - __bfloat162float(hb);
    return ((uint32_t)*(uint16_t*)&hb << 16) | (uint32_t)*(uint16_t*)&ha;
}
__device__ __forceinline__ uint32_t pack_bf2n(float a, float b) {
    __nv_bfloat16 ha = __float2bfloat16(a), hb = __float2bfloat16(b);
    return ((uint32_t)*(uint16_t*)&hb << 16) | (uint32_t)*(uint16_t*)&ha;
}

// ======== 3-term hi/lo GEMM core: 128 thr, tile 128Mx64N, K-chunk 32 =========
// 4 stages x 24KB = 96KB, 2 CTA/SM. Single __syncthreads per chunk:
// load for chunk c+3 targets slot of chunk c-1 (readers already past barrier).
#define MMA_SMEM3 98304

#define GEMM_CORE3()                                                            \
    auto load_stage = [&](int c, int sbuf) {                                    \
        const uint32_t st = sbase + sbuf * 24576;                               \
        const size_t cb = (size_t)c * 64;                                       \
        _Pragma("unroll")                                                       \
        for (int i = 0; i < 4; i++) {                                           \
            const int idx = t + (i << 7);                                       \
            const int row = idx >> 2;                                           \
            const int sc  = (idx & 3) << 4;                                     \
            const uint32_t off = sw64((row << 6) + sc);                         \
            const size_t go = (size_t)row * krow + cb + sc;                     \
            cp16(st + off,        Aph + go);                                    \
            cp16(st + 8192 + off, Apl + go);                                    \
        }                                                                       \
        _Pragma("unroll")                                                       \
        for (int i = 0; i < 2; i++) {                                           \
            const int idx = t + (i << 7);                                       \
            const int row = idx >> 2;                                           \
            const int sc  = (idx & 3) << 4;                                     \
            const uint32_t off = sw64((row << 6) + sc);                         \
            const size_t go = (size_t)row * krow + cb + sc;                     \
            cp16(st + 16384 + off, Bph + go);                                   \
            cp16(st + 20480 + off, Bpl + go);                                   \
        }                                                                       \
        asm volatile("cp.async.commit_group;" ::: "memory");                    \
    };                                                                          \
    load_stage(0, 0); load_stage(1, 1); load_stage(2, 2);                       \
    float acc[2][8][4] = {};                                                    \
    const int arow0 = w * 32 + (lane & 15);                                     \
    const int acb   = (lane >> 4) << 4;                                         \
    const int nrow0 = ((lane >> 4) & 1) * 8 + (lane & 7);                       \
    const int bcb   = ((lane >> 3) & 1) << 4;                                   \
    for (int c = 0; c < KC; c++) {                                              \
        if (c + 2 < KC)      asm volatile("cp.async.wait_group 2;" ::: "memory"); \
        else if (c + 1 < KC) asm volatile("cp.async.wait_group 1;" ::: "memory"); \
        else                 asm volatile("cp.async.wait_group 0;" ::: "memory"); \
        __syncthreads();                                                        \
        if (c + 3 < KC) load_stage(c + 3, (c + 3) & 3);                         \
        const uint32_t sAh = sbase + (c & 3) * 24576;                           \
        const uint32_t sAl = sAh + 8192;                                        \
        const uint32_t sBh = sAh + 16384;                                       \
        const uint32_t sBl = sAh + 20480;                                       \
        _Pragma("unroll")                                                       \
        for (int ks = 0; ks < 2; ks++) {                                        \
            uint32_t ah[2][4], al[2][4];                                        \
            _Pragma("unroll")                                                   \
            for (int mt = 0; mt < 2; mt++) {                                    \
                const uint32_t ro = sw64(((arow0 + mt * 16) << 6) + ks * 32 + acb); \
                ldsm4(ah[mt], sAh + ro);                                        \
                ldsm4(al[mt], sAl + ro);                                        \
            }                                                                   \
            uint32_t bh[4][4], bl_[4][4];                                       \
            _Pragma("unroll")                                                   \
            for (int n4 = 0; n4 < 4; n4++) {                                    \
                const uint32_t ro = sw64(((nrow0 + n4 * 16) << 6) + ks * 32 + bcb); \
                ldsm4(bh[n4], sBh + ro);                                        \
                ldsm4(bl_[n4], sBl + ro);                                       \
            }                                                                   \
            _Pragma("unroll")                                                   \
            for (int mt = 0; mt < 2; mt++)                                      \
                _Pragma("unroll")                                               \
                for (int nt = 0; nt < 8; nt++) {                                \
                    const uint32_t h0 = bh[nt >> 1][(nt & 1) * 2];              \
                    const uint32_t h1 = bh[nt >> 1][(nt & 1) * 2 + 1];          \
                    mma16816(acc[mt][nt], ah[mt], h0, h1);                      \
                    mma16816(acc[mt][nt], al[mt], h0, h1);                      \
                    mma16816(acc[mt][nt], ah[mt],                               \
                             bl_[nt >> 1][(nt & 1) * 2], bl_[nt >> 1][(nt & 1) * 2 + 1]); \
                }                                                               \
        }                                                                       \
    }

// ---------------- final GEMM: out = relu(A2 @ B2^T + bc) --------------------
__global__ void __launch_bounds__(128)
mma_gemm3(const __nv_bfloat16* __restrict__ Ah, const __nv_bfloat16* __restrict__ Al,
          const __nv_bfloat16* __restrict__ Bh, const __nv_bfloat16* __restrict__ Bl,
          const float* __restrict__ bias, float* __restrict__ C, int K, int ldc)
{
    extern __shared__ char sm[];
    const uint32_t sbase = smem_u32(sm);
    const int t = threadIdx.x, lane = t & 31, w = t >> 5;
    const int m0 = blockIdx.y << 7, n0 = blockIdx.x << 6;
    const char* Aph = (const char*)(Ah + (size_t)m0 * K);
    const char* Apl = (const char*)(Al + (size_t)m0 * K);
    const char* Bph = (const char*)(Bh + (size_t)n0 * K);
    const char* Bpl = (const char*)(Bl + (size_t)n0 * K);
    const size_t krow = (size_t)K * 2;
    const int KC = K >> 5;

    GEMM_CORE3()

    const int erow = m0 + w * 32 + (lane >> 2);
    const int ecol = n0 + ((lane & 3) << 1);
    #pragma unroll
    for (int nt = 0; nt < 8; nt++) {
        const int gn = ecol + nt * 8;
        const float2 bb2 = *(const float2*)(bias + gn);
        #pragma unroll
        for (int mt = 0; mt < 2; mt++) {
            #pragma unroll
            for (int half = 0; half < 2; half++) {
                float v0 = fmaxf(acc[mt][nt][half * 2 + 0] + bb2.x, 0.f);
                float v1 = fmaxf(acc[mt][nt][half * 2 + 1] + bb2.y, 0.f);
                const int gm = erow + mt * 16 + half * 8;
                *(float2*)(C + (size_t)gm * ldc + gn) = make_float2(v0, v1);
            }
        }
    }
}

// ---------------- fused QKV GEMM (both blocks via blockIdx.z) ----------------
__global__ void __launch_bounds__(128)
qkv_fused(const __nv_bfloat16* __restrict__ Ah, const __nv_bfloat16* __restrict__ Al,
          const float* __restrict__ bl, const float* __restrict__ bg)
{
    extern __shared__ char sm[];
    const uint32_t sbase = smem_u32(sm);
    const int t = threadIdx.x, lane = t & 31, w = t >> 5;
    const int m0 = blockIdx.y << 7, n0 = blockIdx.x << 6;
    const int z = blockIdx.z;
    const int K = Ee;
    const float* bias = z ? bg : bl;
    const char* Aph = (const char*)(Ah + (size_t)m0 * K);
    const char* Apl = (const char*)(Al + (size_t)m0 * K);
    const char* Bph = (const char*)((z ? g_B1gh : g_B1lh) + (size_t)n0 * K);
    const char* Bpl = (const char*)((z ? g_B1gl : g_B1ll) + (size_t)n0 * K);
    const size_t krow = (size_t)K * 2;
    const int KC = K >> 5;

    GEMM_CORE3()

    const int erow = m0 + w * 32 + (lane >> 2);
    const int ecol = n0 + ((lane & 3) << 1);
    #pragma unroll
    for (int nt = 0; nt < 8; nt++) {
        const int gn = ecol + nt * 8;
        const float2 bb2 = *(const float2*)(bias + gn);
        #pragma unroll
        for (int mt = 0; mt < 2; mt++) {
            #pragma unroll
            for (int half = 0; half < 2; half++) {
                const float v0 = acc[mt][nt][half * 2 + 0] + bb2.x;
                const float v1 = acc[mt][nt][half * 2 + 1] + bb2.y;
                const int gm = erow + mt * 16 + half * 8;
                if (z == 0) {
                    *(float2*)(g_qkv_l + (size_t)gm * QKVN + gn) = make_float2(v0, v1);
                } else if (n0 < 1024) {
                    float r0, r1;
                    const uint32_t hi = pack_bf2(v0, v1, r0, r1);
                    const uint32_t lo = pack_bf2n(r0, r1);
                    *(uint32_t*)(g_qk_h + (size_t)gm * 1024 + gn) = hi;
                    *(uint32_t*)(g_qk_l + (size_t)gm * 1024 + gn) = lo;
                } else {
                    *(float2*)(g_vg + (size_t)gm * Ee + (gn - 1024)) = make_float2(v0, v1);
                }
            }
        }
    }
}

// ---------------- merged input splits (homogeneous) ---------------------------
__global__ void split_all(const float* __restrict__ x,
                          const float* __restrict__ Wl_in,
                          const float* __restrict__ Wg_in)
{
    const int b = blockIdx.x;
    const float* in;
    __nv_bfloat16 *oh, *ol;
    int bid;
    if (b < 4096)      { in = x;     oh = g_A1h;  ol = g_A1l;  bid = b; }
    else if (b < 4864) { in = Wl_in; oh = g_B1lh; ol = g_B1ll; bid = b - 4096; }
    else               { in = Wg_in; oh = g_B1gh; ol = g_B1gl; bid = b - 4864; }
    const size_t i = ((size_t)bid * 256 + threadIdx.x) << 2;
    const float4 v = *(const float4*)(in + i);
    float vv[4] = {v.x, v.y, v.z, v.w};
    union { __nv_bfloat16 bb[4]; uint2 u; } hu, lu;
    #pragma unroll
    for (int j = 0; j < 4; j++) {
        hu.bb[j] = __float2bfloat16(vv[j]);
        lu.bb[j] = __float2bfloat16(vv[j] - __bfloat162float(hu.bb[j]));
    }
    *(uint2*)(oh + i) = hu.u;
    *(uint2*)(ol + i) = lu.u;
}

// split2 for Wc
__global__ void split2(const float* __restrict__ in,
                       __nv_bfloat16* __restrict__ oh, __nv_bfloat16* __restrict__ ol)
{
    const size_t i = ((size_t)blockIdx.x * 256 + threadIdx.x) << 2;
    const float4 v = *(const float4*)(in + i);
    float vv[4] = {v.x, v.y, v.z, v.w};
    union { __nv_bfloat16 b[4]; uint2 u; } hu, lu;
    #pragma unroll
    for (int j = 0; j < 4; j++) {
        hu.b[j] = __float2bfloat16(vv[j]);
        lu.b[j] = __float2bfloat16(vv[j] - __bfloat162float(hu.b[j]));
    }
    *(uint2*)(oh + i) = hu.u;
    *(uint2*)(ol + i) = lu.u;
}

// transpose + split V
__global__ void __launch_bounds__(256)
vt_split(const float* __restrict__ vg,
         __nv_bfloat16* __restrict__ vh, __nv_bfloat16* __restrict__ vl)
{
    __shared__ float tile[64][65];
    const int t = threadIdx.x;
    const int bh = blockIdx.y, b = bh >> 3, h = bh & 7;
    const int s0 = blockIdx.x << 6;
    #pragma unroll
    for (int i = 0; i < 4; i++) {
        const int idx = t + (i << 8);
        const int row = idx >> 4, c4 = (idx & 15) << 2;
        float4 v = *(const float4*)(vg + (size_t)(b * Ss + s0 + row) * Ee + h * 64 + c4);
        tile[row][c4] = v.x; tile[row][c4 + 1] = v.y;
        tile[row][c4 + 2] = v.z; tile[row][c4 + 3] = v.w;
    }
    __syncthreads();
    #pragma unroll
    for (int i = 0; i < 4; i++) {
        const int idx = t + (i << 8);
        const int d = idx >> 4, sc = (idx & 15) << 2;
        uint16_t hh[4], ll[4];
        #pragma unroll
        for (int k = 0; k < 4; k++) {
            const float f = tile[sc + k][d];
            __nv_bfloat16 hb = __float2bfloat16(f);
            const float lf = f - __bfloat162float(hb);
            __nv_bfloat16 lb = __float2bfloat16(lf);
            hh[k] = *(uint16_t*)&hb; ll[k] = *(uint16_t*)&lb;
        }
        uint2 hv = make_uint2((uint32_t)hh[0] | ((uint32_t)hh[1] << 16),
                              (uint32_t)hh[2] | ((uint32_t)hh[3] << 16));
        uint2 lv = make_uint2((uint32_t)ll[0] | ((uint32_t)ll[1] << 16),
                              (uint32_t)ll[2] | ((uint32_t)ll[3] << 16));
        *(uint2*)(vh + (size_t)(bh * 64 + d) * Ss + s0 + sc) = hv;
        *(uint2*)(vl + (size_t)(bh * 64 + d) * Ss + s0 + sc) = lv;
    }
}

// ---------------- flash attention: 128 threads, 64-query tiles ---------------
#define AT_SMEM 81920

__global__ void __launch_bounds__(128)
flash_attn(const __nv_bfloat16* __restrict__ qkh, const __nv_bfloat16* __restrict__ qkl,
           const __nv_bfloat16* __restrict__ vth, const __nv_bfloat16* __restrict__ vtl)
{
    extern __shared__ char sm[];
    const uint32_t sb = smem_u32(sm);
    const int t = threadIdx.x, lane = t & 31, w = t >> 5;
    const int bh = blockIdx.y, b = bh >> 3, h = bh & 7;
    const int q0 = blockIdx.x << 6;
    const uint32_t Qh = sb, Ql = sb + 8192;

    {
        const char* srch = (const char*)(qkh + (size_t)(b * Ss + q0) * 1024 + h * 64);
        const char* srcl = (const char*)(qkl + (size_t)(b * Ss + q0) * 1024 + h * 64);
        #pragma unroll
        for (int i = 0; i < 4; i++) {
            const int idx = t + (i << 7);
            const int row = idx >> 3, ch = (idx & 7) << 4;
            const uint32_t off = sw128((row << 7) | ch);
            cp16(Qh + off, srch + (size_t)row * 2048 + ch);
            cp16(Ql + off, srcl + (size_t)row * 2048 + ch);
        }
        asm volatile("cp.async.commit_group;" ::: "memory");
    }

    auto load_kv = [&](int kt, int buf) {
        const uint32_t bb = sb + 16384 + buf * 32768;
        const char* kh = (const char*)(qkh + (size_t)(b * Ss + kt * 64) * 1024 + 512 + h * 64);
        const char* kl = (const char*)(qkl + (size_t)(b * Ss + kt * 64) * 1024 + 512 + h * 64);
        const char* vh = (const char*)(vth + (size_t)(bh * 64) * Ss + kt * 64);
        const char* vl = (const char*)(vtl + (size_t)(bh * 64) * Ss + kt * 64);
        #pragma unroll
        for (int i = 0; i < 4; i++) {
            const int idx = t + (i << 7);
            const int row = idx >> 3, ch = (idx & 7) << 4;
            const uint32_t off = sw128((row << 7) | ch);
            cp16(bb + off,         kh + (size_t)row * 2048 + ch);
            cp16(bb + 8192 + off,  kl + (size_t)row * 2048 + ch);
            cp16(bb + 16384 + off, vh + (size_t)row * 2048 + ch);
            cp16(bb + 24576 + off, vl + (size_t)row * 2048 + ch);
        }
        asm volatile("cp.async.commit_group;" ::: "memory");
    };
    load_kv(0, 0);
    load_kv(1, 1);

    asm volatile("cp.async.wait_group 2;" ::: "memory");
    __syncthreads();

    const int arow = (w << 4) + (lane & 15);
    const int acb  = (lane >> 4) << 4;
    uint32_t qh[4][4], ql[4][4];
    #pragma unroll
    for (int ks = 0; ks < 4; ks++) {
        ldsm4(qh[ks], Qh + sw128((arow << 7) + ks * 32 + acb));
        ldsm4(ql[ks], Ql + sw128((arow << 7) + ks * 32 + acb));
    }

    const int nrow = ((lane >> 4) & 1) * 8 + (lane & 7);
    const int bcb  = ((lane >> 3) & 1) << 4;

    float o[8][4] = {};
    float m0 = -INFINITY, m1 = -INFINITY, l0 = 0.f, l1 = 0.f;

    for (int kt = 0; kt < 16; kt++) {
        const int buf = kt & 1;
        if (kt + 1 < 16) asm volatile("cp.async.wait_group 1;" ::: "memory");
        else             asm volatile("cp.async.wait_group 0;" ::: "memory");
        __syncthreads();
        const uint32_t Kh = sb + 16384 + buf * 32768;
        const uint32_t Kl = Kh + 8192, Vh = Kh + 16384, Vl = Kh + 24576;

        float sA[8][4] = {};
        #pragma unroll
        for (int ks = 0; ks < 4; ks++) {
            uint32_t kf[4][4], lf[4][4];
            #pragma unroll
            for (int n4 = 0; n4 < 4; n4++) {
                const uint32_t ro = sw128(((nrow + n4 * 16) << 7) + ks * 32 + bcb);
                ldsm4(kf[n4], Kh + ro);
                ldsm4(lf[n4], Kl + ro);
            }
            #pragma unroll
            for (int nt = 0; nt < 8; nt++) {
                const uint32_t b0 = kf[nt >> 1][(nt & 1) * 2];
                const uint32_t b1 = kf[nt >> 1][(nt & 1) * 2 + 1];
                mma16816(sA[nt], qh[ks], b0, b1);
                mma16816(sA[nt], ql[ks], b0, b1);
                mma16816(sA[nt], qh[ks],
                         lf[nt >> 1][(nt & 1) * 2], lf[nt >> 1][(nt & 1) * 2 + 1]);
            }
        }

        float rm0 = -INFINITY, rm1 = -INFINITY;
        #pragma unroll
        for (int nt = 0; nt < 8; nt++) {
            #pragma unroll
            for (int j = 0; j < 4; j++) sA[nt][j] *= 0.125f;
            rm0 = fmaxf(rm0, fmaxf(sA[nt][0], sA[nt][1]));
            rm1 = fmaxf(rm1, fmaxf(sA[nt][2], sA[nt][3]));
        }
        rm0 = fmaxf(rm0, __shfl_xor_sync(0xffffffffu, rm0, 1));
        rm0 = fmaxf(rm0, __shfl_xor_sync(0xffffffffu, rm0, 2));
        rm1 = fmaxf(rm1, __shfl_xor_sync(0xffffffffu, rm1, 1));
        rm1 = fmaxf(rm1, __shfl_xor_sync(0xffffffffu, rm1, 2));
        const float mn0 = fmaxf(m0, rm0), mn1 = fmaxf(m1, rm1);
        const float sc0 = __expf(m0 - mn0), sc1 = __expf(m1 - mn1);
        m0 = mn0; m1 = mn1;

        float ps0 = 0.f, ps1 = 0.f;
        uint32_t phi[4][4], plo[4][4];
        #pragma unroll
        for (int j = 0; j < 4; j++) {
            float p[2][4];
            #pragma unroll
            for (int e = 0; e < 2; e++) {
                p[e][0] = __expf(sA[2 * j + e][0] - mn0);
                p[e][1] = __expf(sA[2 * j + e][1] - mn0);
                p[e][2] = __expf(sA[2 * j + e][2] - mn1);
                p[e][3] = __expf(sA[2 * j + e][3] - mn1);
                ps0 += p[e][0] + p[e][1];
                ps1 += p[e][2] + p[e][3];
            }
            float r0, r1;
            phi[j][0] = pack_bf2(p[0][0], p[0][1], r0, r1); plo[j][0] = pack_bf2n(r0, r1);
            phi[j][1] = pack_bf2(p[0][2], p[0][3], r0, r1); plo[j][1] = pack_bf2n(r0, r1);
            phi[j][2] = pack_bf2(p[1][0], p[1][1], r0, r1); plo[j][2] = pack_bf2n(r0, r1);
            phi[j][3] = pack_bf2(p[1][2], p[1][3], r0, r1); plo[j][3] = pack_bf2n(r0, r1);
        }
        l0 = l0 * sc0 + ps0;
        l1 = l1 * sc1 + ps1;
        #pragma unroll
        for (int nt = 0; nt < 8; nt++) {
            o[nt][0] *= sc0; o[nt][1] *= sc0;
            o[nt][2] *= sc1; o[nt][3] *= sc1;
        }

        #pragma unroll
        for (int ks = 0; ks < 4; ks++) {
            uint32_t bv[4][4];
            #pragma unroll
            for (int n4 = 0; n4 < 4; n4++)
                ldsm4(bv[n4], Vh + sw128(((nrow + n4 * 16) << 7) + ks * 32 + bcb));
            #pragma unroll
            for (int nt = 0; nt < 8; nt++) {
                mma16816(o[nt], phi[ks], bv[nt >> 1][(nt & 1) * 2], bv[nt >> 1][(nt & 1) * 2 + 1]);
                mma16816(o[nt], plo[ks], bv[nt >> 1][(nt & 1) * 2], bv[nt >> 1][(nt & 1) * 2 + 1]);
            }
            #pragma unroll
            for (int n4 = 0; n4 < 4; n4++)
                ldsm4(bv[n4], Vl + sw128(((nrow + n4 * 16) << 7) + ks * 32 + bcb));
            #pragma unroll
            for (int nt = 0; nt < 8; nt++)
                mma16816(o[nt], phi[ks], bv[nt >> 1][(nt & 1) * 2], bv[nt >> 1][(nt & 1) * 2 + 1]);
        }
        __syncthreads();
        if (kt + 2 < 16) load_kv(kt + 2, buf);
    }

    l0 += __shfl_xor_sync(0xffffffffu, l0, 1);
    l0 += __shfl_xor_sync(0xffffffffu, l0, 2);
    l1 += __shfl_xor_sync(0xffffffffu, l1, 1);
    l1 += __shfl_xor_sync(0xffffffffu, l1, 2);
    const float i0 = 1.f / l0, i1 = 1.f / l1;
    const int r = lane >> 2, c2 = (lane & 3) << 1;
    const int row0 = b * Ss + q0 + (w << 4) + r;
    __nv_bfloat16* ha = g_A2h + (size_t)row0 * 1024;
    __nv_bfloat16* la = g_A2l + (size_t)row0 * 1024;
    __nv_bfloat16* hb2 = g_A2h + (size_t)(row0 + 8) * 1024;
    __nv_bfloat16* lb2 = g_A2l + (size_t)(row0 + 8) * 1024;
    #pragma unroll
    for (int nt = 0; nt < 8; nt++) {
        const int col = 512 + h * 64 + nt * 8 + c2;
        float r0, r1;
        uint32_t hi = pack_bf2(o[nt][0] * i0, o[nt][1] * i0, r0, r1);
        uint32_t lo = pack_bf2n(r0, r1);
        *(uint32_t*)(ha + col) = hi;
        *(uint32_t*)(la + col) = lo;
        hi = pack_bf2(o[nt][2] * i1, o[nt][3] * i1, r0, r1);
        lo = pack_bf2n(r0, r1);
        *(uint32_t*)(hb2 + col) = hi;
        *(uint32_t*)(lb2 + col) = lo;
    }
}

// ---------------- fp32 SIMT GEMM for Wc (double-buffered) --------------------
__global__ void __launch_bounds__(256)
wc_gemm(const float* __restrict__ Wf, const float* __restrict__ Wl_out,
        const float* __restrict__ Wg_out, float* __restrict__ Wc)
{
    __shared__ float As[2][16][68];
    __shared__ float Bs[2][16][68];
    const int g = blockIdx.z;
    const float* A = Wf + (g ? Ee : 0);
    const float* W = g ? Wg_out : Wl_out;
    float* C = Wc + (g ? Ee : 0);
    const int t = threadIdx.x, tx = t & 15, ty = t >> 4;
    const int m0 = blockIdx.y * 64, n0 = blockIdx.x * 64;
    const int lr = t >> 2, lk = (t & 3) << 2;
    const int bkk = t >> 4, bcc = (t & 15) << 2;
    float acc[4][4] = {};

    float4 va = *(const float4*)(A + (size_t)(m0 + lr) * (2 * Ee) + lk);
    float4 vb = *(const float4*)(W + (size_t)bkk * Ee + n0 + bcc);
    int buf = 0;
    for (int k0 = 0; k0 < Ee; k0 += 16) {
        As[buf][lk + 0][lr] = va.x; As[buf][lk + 1][lr] = va.y;
        As[buf][lk + 2][lr] = va.z; As[buf][lk + 3][lr] = va.w;
        *(float4*)&Bs[buf][bkk][bcc] = vb;
        __syncthreads();
        if (k0 + 16 < Ee) {
            va = *(const float4*)(A + (size_t)(m0 + lr) * (2 * Ee) + k0 + 16 + lk);
            vb = *(const float4*)(W + (size_t)(k0 + 16 + bkk) * Ee + n0 + bcc);
        }
        #pragma unroll
        for (int kk = 0; kk < 16; kk++) {
            float4 a = *(const float4*)&As[buf][kk][ty << 2];
            float4 b = *(const float4*)&Bs[buf][kk][tx << 2];
            float av[4] = {a.x, a.y, a.z, a.w};
            float bv[4] = {b.x, b.y, b.z, b.w};
            #pragma unroll
            for (int i = 0; i < 4; i++)
                #pragma unroll
                for (int j = 0; j < 4; j++)
                    acc[i][j] = fmaf(av[i], bv[j], acc[i][j]);
        }
        buf ^= 1;
    }
    #pragma unroll
    for (int i = 0; i < 4; i++)
        *(float4*)(C + (size_t)(m0 + (ty << 2) + i) * (2 * Ee) + n0 + (tx << 2)) =
            make_float4(acc[i][0], acc[i][1], acc[i][2], acc[i][3]);
}

// ---------------- combined bias ----------------------------------------------
__global__ void __launch_bounds__(128)
bias_combine_kernel(const float* __restrict__ Wf,
                    const float* __restrict__ bl,
                    const float* __restrict__ bg,
                    const float* __restrict__ bf)
{
    const int o = blockIdx.x;
    const int t = threadIdx.x;
    const float* row = Wf + (size_t)o * (2 * Ee);
    float acc = 0.f;
    for (int j = t; j < Ee; j += 128)
        acc += row[j] * bl[j] + row[Ee + j] * bg[j];
    #pragma unroll
    for (int off = 16; off; off >>= 1)
        acc += __shfl_xor_sync(0xffffffffu, acc, off);
    __shared__ float ws[4];
    if ((t & 31) == 0) ws[t >> 5] = acc;
    __syncthreads();
    if (t == 0) g_bc[o] = ws[0] + ws[1] + ws[2] + ws[3] + bf[o];
}

// ---------------- local attention v2: smem-tiled K/V window ------------------
// grid (Ss/128, B*H), 256 threads. CTA loads K/V rows [q0-3, q0+130] once.
#define LA_SMEM (2 * 134 * 64 * 4)   // 68608 B

__global__ void __launch_bounds__(256)
local_attn_kernel(const float* __restrict__ qkv)
{
    extern __shared__ float las[];
    float* Ks = las;                 // [134][64]
    float* Vs = las + 134 * 64;
    const int t = threadIdx.x;
    const int bh = blockIdx.y, b = bh >> 3, h = bh & 7;
    const int q0 = blockIdx.x << 7;
    const float* base = qkv + (size_t)(b * Ss) * QKVN + h * DHd;

    for (int idx = t; idx < 134 * 16; idx += 256) {
        const int sr = idx >> 4;
        const int c4 = (idx & 15) << 2;
        const int gr = q0 - 3 + sr;
        if (gr >= 0 && gr < Ss) {
            *(float4*)&Ks[sr * 64 + c4] =
                *(const float4*)(base + (size_t)gr * QKVN + Ee + c4);
            *(float4*)&Vs[sr * 64 + c4] =
                *(const float4*)(base + (size_t)gr * QKVN + 2 * Ee + c4);
        } else {
            *(float4*)&Ks[sr * 64 + c4] = make_float4(0.f, 0.f, 0.f, 0.f);
            *(float4*)&Vs[sr * 64 + c4] = make_float4(0.f, 0.f, 0.f, 0.f);
        }
    }
    __syncthreads();

    const int w = t >> 5, lane = t & 31;
    for (int qi = 0; qi < 16; qi++) {
        const int q = q0 + (w << 4) + qi;
        const float* qrow = base + (size_t)q * QKVN;
        const float qv0 = qrow[lane], qv1 = qrow[lane + 32];
        const int srb = q - q0;           // smem row of neighbor jj: srb + jj

        float s[7];
        float mmax = -1e30f;
        #pragma unroll
        for (int jj = 0; jj < 7; jj++) {
            const int j = q - LOCALW + jj;
            const bool valid = (j >= 0) && (j < Ss);
            const float* kr = Ks + (srb + jj) * 64;
            float d = qv0 * kr[lane] + qv1 * kr[lane + 32];
            #pragma unroll
            for (int off = 16; off; off >>= 1)
                d += __shfl_xor_sync(0xffffffffu, d, off);
            d = valid ? d * 0.125f : -1e30f;
            s[jj] = d;
            mmax = fmaxf(mmax, d);
        }
        float sum = 0.f;
        #pragma unroll
        for (int jj = 0; jj < 7; jj++) { s[jj] = __expf(s[jj] - mmax); sum += s[jj]; }
        const float inv = 1.f / sum;
        float o0 = 0.f, o1 = 0.f;
        #pragma unroll
        for (int jj = 0; jj < 7; jj++) {
            const float* vr = Vs + (srb + jj) * 64;
            o0 = fmaf(s[jj], vr[lane],      o0);
            o1 = fmaf(s[jj], vr[lane + 32], o1);
        }
        const float v0 = o0 * inv, v1 = o1 * inv;
        const float p0 = __shfl_down_sync(0xffffffffu, v0, 1);
        const float p1 = __shfl_down_sync(0xffffffffu, v1, 1);
        if (!(lane & 1)) {
            __nv_bfloat16* a2h = g_A2h + (size_t)(b * Ss + q) * 1024;
            __nv_bfloat16* a2l = g_A2l + (size_t)(b * Ss + q) * 1024;
            const int c0 = h * DHd + lane;
            float r0, r1;
            uint32_t hi = pack_bf2(v0, p0, r0, r1);
            uint32_t lo = pack_bf2n(r0, r1);
            *(uint32_t*)(a2h + c0) = hi;
            *(uint32_t*)(a2l + c0) = lo;
            hi = pack_bf2(v1, p1, r0, r1);
            lo = pack_bf2n(r0, r1);
            *(uint32_t*)(a2h + c0 + 32) = hi;
            *(uint32_t*)(a2l + c0 + 32) = lo;
        }
    }
}

// ---------------- launcher -----------------------------------------------------
extern "C" void kernel_launch(void* const* d_in, const int* in_sizes, int n_in,
                              void* d_out, int out_size)
{
    (void)in_sizes; (void)n_in; (void)out_size;
    const float* x      = (const float*)d_in[0];
    const float* Wl_in  = (const float*)d_in[1];
    const float* bl_in  = (const float*)d_in[2];
    const float* Wl_out = (const float*)d_in[3];
    const float* bl_out = (const float*)d_in[4];
    const float* Wg_in  = (const float*)d_in[5];
    const float* bg_in  = (const float*)d_in[6];
    const float* Wg_out = (const float*)d_in[7];
    const float* bg_out = (const float*)d_in[8];
    const float* Wf     = (const float*)d_in[9];
    const float* bf     = (const float*)d_in[10];
    float* out = (float*)d_out;

    float *qkv_l, *vg, *Wc, *bc;
    __nv_bfloat16 *A1h, *A1l, *A2h, *A2l, *B2h, *B2l, *qkh, *qkl, *vth, *vtl;
    cudaGetSymbolAddress((void**)&qkv_l, g_qkv_l);
    cudaGetSymbolAddress((void**)&vg,    g_vg);
    cudaGetSymbolAddress((void**)&Wc,    g_Wc);
    cudaGetSymbolAddress((void**)&bc,    g_bc);
    cudaGetSymbolAddress((void**)&A1h,   g_A1h);
    cudaGetSymbolAddress((void**)&A1l,   g_A1l);
    cudaGetSymbolAddress((void**)&A2h,   g_A2h);
    cudaGetSymbolAddress((void**)&A2l,   g_A2l);
    cudaGetSymbolAddress((void**)&B2h,   g_B2h);
    cudaGetSymbolAddress((void**)&B2l,   g_B2l);
    cudaGetSymbolAddress((void**)&qkh,   g_qk_h);
    cudaGetSymbolAddress((void**)&qkl,   g_qk_l);
    cudaGetSymbolAddress((void**)&vth,   g_vt_h);
    cudaGetSymbolAddress((void**)&vtl,   g_vt_l);

    cudaFuncSetAttribute(mma_gemm3,
                         cudaFuncAttributeMaxDynamicSharedMemorySize, MMA_SMEM3);
    cudaFuncSetAttribute(qkv_fused,
                         cudaFuncAttributeMaxDynamicSharedMemorySize, MMA_SMEM3);
    cudaFuncSetAttribute(flash_attn,
                         cudaFuncAttributeMaxDynamicSharedMemorySize, AT_SMEM);
    cudaFuncSetAttribute(local_attn_kernel,
                         cudaFuncAttributeMaxDynamicSharedMemorySize, LA_SMEM);

    // L1: all input hi/lo splits
    split_all<<<5632, 256>>>(x, Wl_in, Wg_in);

    // L2-L4: wc chain
    wc_gemm<<<dim3(8, 8, 2), 256>>>(Wf, Wl_out, Wg_out, Wc);
    bias_combine_kernel<<<Ee, 128>>>(Wf, bl_out, bg_out, bf);
    split2<<<(Ee * 2 * Ee) / 1024, 256>>>(Wc, B2h, B2l);

    // L5: fused QKV projections
    qkv_fused<<<dim3(QKVN / 64, Mm / 128, 2), 128, MMA_SMEM3>>>(
        A1h, A1l, bl_in, bg_in);

    // L6: local attention (smem-tiled) -> A2
    local_attn_kernel<<<dim3(Ss / 128, Bb * Hh), 256, LA_SMEM>>>(qkv_l);

    // L7: V transpose-split
    vt_split<<<dim3(Ss / 64, Bb * Hh), 256>>>(vg, vth, vtl);

    // L8: flash attention -> A2
    flash_attn<<<dim3(Ss / 64, Bb * Hh), 128, AT_SMEM>>>(qkh, qkl, vth, vtl);

    // L9: final fused projection + ReLU
    mma_gemm3<<<dim3(Ee / 64, Mm / 128), 128, MMA_SMEM3>>>(
        A2h, A2l, B2h, B2l, bc, out, 1024, Ee);
}

// round 15
// speedup vs baseline: 1.0464x; 1.0464x over previous
#include <cuda_runtime.h>
#include <cuda_bf16.h>
#include <math.h>
#include <stdint.h>

// Problem constants
#define Bb   8
#define Ss   1024
#define Ee   512
#define Hh   8
#define DHd  64
#define Mm   (Bb * Ss)        // 8192
#define QKVN (3 * Ee)         // 1536
#define LOCALW 3

// ---------------- scratch (device globals) ----------------------------------
__device__ float g_qkv_l[(size_t)Mm * QKVN];
__device__ float g_vg   [(size_t)Mm * Ee];
__device__ float g_Wc   [(size_t)Ee * 2 * Ee];
__device__ float g_bc   [Ee];
__device__ __nv_bfloat16 g_A1h[(size_t)Mm * Ee];
__device__ __nv_bfloat16 g_A1l[(size_t)Mm * Ee];
__device__ __nv_bfloat16 g_B1lh[(size_t)QKVN * Ee];
__device__ __nv_bfloat16 g_B1ll[(size_t)QKVN * Ee];
__device__ __nv_bfloat16 g_B1gh[(size_t)QKVN * Ee];
__device__ __nv_bfloat16 g_B1gl[(size_t)QKVN * Ee];
__device__ __nv_bfloat16 g_A2h[(size_t)Mm * 1024];
__device__ __nv_bfloat16 g_A2l[(size_t)Mm * 1024];
__device__ __nv_bfloat16 g_B2h[(size_t)Ee * 1024];
__device__ __nv_bfloat16 g_B2l[(size_t)Ee * 1024];
__device__ __nv_bfloat16 g_qk_h[(size_t)Mm * 1024];
__device__ __nv_bfloat16 g_qk_l[(size_t)Mm * 1024];
__device__ __nv_bfloat16 g_vt_h[(size_t)64 * 64 * Ss];
__device__ __nv_bfloat16 g_vt_l[(size_t)64 * 64 * Ss];

// ---------------- PTX helpers (base ISA only) --------------------------------
__device__ __forceinline__ uint32_t smem_u32(const void* p) {
    uint32_t a;
    asm("{ .reg .u64 t; cvta.to.shared.u64 t, %1; cvt.u32.u64 %0, t; }"
        : "=r"(a) : "l"(p));
    return a;
}
__device__ __forceinline__ uint32_t sw128(uint32_t o) { return o ^ ((o >> 3) & 0x70); }
__device__ __forceinline__ uint32_t sw64(uint32_t o)  { return o ^ ((o >> 3) & 0x30); }

__device__ __forceinline__ void cp16(uint32_t dst, const void* src) {
    asm volatile("cp.async.cg.shared.global [%0], [%1], 16;"
                 :: "r"(dst), "l"(src) : "memory");
}
__device__ __forceinline__ void ldsm4(uint32_t* d, uint32_t a) {
    asm volatile("ldmatrix.sync.aligned.m8n8.x4.shared.b16 {%0,%1,%2,%3}, [%4];"
                 : "=r"(d[0]), "=r"(d[1]), "=r"(d[2]), "=r"(d[3]) : "r"(a));
}
__device__ __forceinline__ void mma16816(float* c, const uint32_t* a,
                                         uint32_t b0, uint32_t b1) {
    asm volatile("mma.sync.aligned.m16n8k16.row.col.f32.bf16.bf16.f32 "
                 "{%0,%1,%2,%3}, {%4,%5,%6,%7}, {%8,%9}, {%0,%1,%2,%3};"
                 : "+f"(c[0]), "+f"(c[1]), "+f"(c[2]), "+f"(c[3])
                 : "r"(a[0]), "r"(a[1]), "r"(a[2]), "r"(a[3]), "r"(b0), "r"(b1));
}
__device__ __forceinline__ uint32_t pack_bf2(float a, float b, float& ra, float& rb) {
    __nv_bfloat16 ha = __float2bfloat16(a), hb = __float2bfloat16(b);
    ra = a - __bfloat162float(ha);
    rb = b - __bfloat162float(hb);
    return ((uint32_t)*(uint16_t*)&hb << 16) | (uint32_t)*(uint16_t*)&ha;
}
__device__ __forceinline__ uint32_t pack_bf2n(float a, float b) {
    __nv_bfloat16 ha = __float2bfloat16(a), hb = __float2bfloat16(b);
    return ((uint32_t)*(uint16_t*)&hb << 16) | (uint32_t)*(uint16_t*)&ha;
}

// ======== 3-term hi/lo GEMM core: 128 thr, tile 128Mx64N, K-chunk 32 =========
// 4 stages x 24KB = 96KB (2 CTA/SM); ONE __syncthreads per chunk. Load for
// chunk c+3 reuses slot of chunk c-1, whose readers finished before this
// barrier. This is the ONLY change vs the proven round-11 kernel.
#define MMA_SMEM3 98304

#define GEMM_CORE3()                                                            \
    auto load_stage = [&](int c, int sbuf) {                                    \
        const uint32_t st = sbase + sbuf * 24576;                               \
        const size_t cb = (size_t)c * 64;                                       \
        _Pragma("unroll")                                                       \
        for (int i = 0; i < 4; i++) {                                           \
            const int idx = t + (i << 7);                                       \
            const int row = idx >> 2;                                           \
            const int sc  = (idx & 3) << 4;                                     \
            const uint32_t off = sw64((row << 6) + sc);                         \
            const size_t go = (size_t)row * krow + cb + sc;                     \
            cp16(st + off,        Aph + go);                                    \
            cp16(st + 8192 + off, Apl + go);                                    \
        }                                                                       \
        _Pragma("unroll")                                                       \
        for (int i = 0; i < 2; i++) {                                           \
            const int idx = t + (i << 7);                                       \
            const int row = idx >> 2;                                           \
            const int sc  = (idx & 3) << 4;                                     \
            const uint32_t off = sw64((row << 6) + sc);                         \
            const size_t go = (size_t)row * krow + cb + sc;                     \
            cp16(st + 16384 + off, Bph + go);                                   \
            cp16(st + 20480 + off, Bpl + go);                                   \
        }                                                                       \
        asm volatile("cp.async.commit_group;" ::: "memory");                    \
    };                                                                          \
    load_stage(0, 0); load_stage(1, 1); load_stage(2, 2);                       \
    float acc[2][8][4] = {};                                                    \
    const int arow0 = w * 32 + (lane & 15);                                     \
    const int acb   = (lane >> 4) << 4;                                         \
    const int nrow0 = ((lane >> 4) & 1) * 8 + (lane & 7);                       \
    const int bcb   = ((lane >> 3) & 1) << 4;                                   \
    for (int c = 0; c < KC; c++) {                                              \
        if (c + 2 < KC)      asm volatile("cp.async.wait_group 2;" ::: "memory"); \
        else if (c + 1 < KC) asm volatile("cp.async.wait_group 1;" ::: "memory"); \
        else                 asm volatile("cp.async.wait_group 0;" ::: "memory"); \
        __syncthreads();                                                        \
        if (c + 3 < KC) load_stage(c + 3, (c + 3) & 3);                         \
        const uint32_t sAh = sbase + (c & 3) * 24576;                           \
        const uint32_t sAl = sAh + 8192;                                        \
        const uint32_t sBh = sAh + 16384;                                       \
        const uint32_t sBl = sAh + 20480;                                       \
        _Pragma("unroll")                                                       \
        for (int ks = 0; ks < 2; ks++) {                                        \
            uint32_t ah[2][4], al[2][4];                                        \
            _Pragma("unroll")                                                   \
            for (int mt = 0; mt < 2; mt++) {                                    \
                const uint32_t ro = sw64(((arow0 + mt * 16) << 6) + ks * 32 + acb); \
                ldsm4(ah[mt], sAh + ro);                                        \
                ldsm4(al[mt], sAl + ro);                                        \
            }                                                                   \
            uint32_t bh[4][4], bl_[4][4];                                       \
            _Pragma("unroll")                                                   \
            for (int n4 = 0; n4 < 4; n4++) {                                    \
                const uint32_t ro = sw64(((nrow0 + n4 * 16) << 6) + ks * 32 + bcb); \
                ldsm4(bh[n4], sBh + ro);                                        \
                ldsm4(bl_[n4], sBl + ro);                                       \
            }                                                                   \
            _Pragma("unroll")                                                   \
            for (int mt = 0; mt < 2; mt++)                                      \
                _Pragma("unroll")                                               \
                for (int nt = 0; nt < 8; nt++) {                                \
                    const uint32_t h0 = bh[nt >> 1][(nt & 1) * 2];              \
                    const uint32_t h1 = bh[nt >> 1][(nt & 1) * 2 + 1];          \
                    mma16816(acc[mt][nt], ah[mt], h0, h1);                      \
                    mma16816(acc[mt][nt], al[mt], h0, h1);                      \
                    mma16816(acc[mt][nt], ah[mt],                               \
                             bl_[nt >> 1][(nt & 1) * 2], bl_[nt >> 1][(nt & 1) * 2 + 1]); \
                }                                                               \
        }                                                                       \
    }

// ---------------- final GEMM: out = relu(A2 @ B2^T + bc) --------------------
__global__ void __launch_bounds__(128)
mma_gemm3(const __nv_bfloat16* __restrict__ Ah, const __nv_bfloat16* __restrict__ Al,
          const __nv_bfloat16* __restrict__ Bh, const __nv_bfloat16* __restrict__ Bl,
          const float* __restrict__ bias, float* __restrict__ C, int K, int ldc)
{
    extern __shared__ char sm[];
    const uint32_t sbase = smem_u32(sm);
    const int t = threadIdx.x, lane = t & 31, w = t >> 5;
    const int m0 = blockIdx.y << 7, n0 = blockIdx.x << 6;
    const char* Aph = (const char*)(Ah + (size_t)m0 * K);
    const char* Apl = (const char*)(Al + (size_t)m0 * K);
    const char* Bph = (const char*)(Bh + (size_t)n0 * K);
    const char* Bpl = (const char*)(Bl + (size_t)n0 * K);
    const size_t krow = (size_t)K * 2;
    const int KC = K >> 5;

    GEMM_CORE3()

    const int erow = m0 + w * 32 + (lane >> 2);
    const int ecol = n0 + ((lane & 3) << 1);
    #pragma unroll
    for (int nt = 0; nt < 8; nt++) {
        const int gn = ecol + nt * 8;
        const float2 bb2 = *(const float2*)(bias + gn);
        #pragma unroll
        for (int mt = 0; mt < 2; mt++) {
            #pragma unroll
            for (int half = 0; half < 2; half++) {
                float v0 = fmaxf(acc[mt][nt][half * 2 + 0] + bb2.x, 0.f);
                float v1 = fmaxf(acc[mt][nt][half * 2 + 1] + bb2.y, 0.f);
                const int gm = erow + mt * 16 + half * 8;
                *(float2*)(C + (size_t)gm * ldc + gn) = make_float2(v0, v1);
            }
        }
    }
}

// ---------------- fused QKV GEMM (both blocks via blockIdx.z) ----------------
__global__ void __launch_bounds__(128)
qkv_fused(const __nv_bfloat16* __restrict__ Ah, const __nv_bfloat16* __restrict__ Al,
          const float* __restrict__ bl, const float* __restrict__ bg)
{
    extern __shared__ char sm[];
    const uint32_t sbase = smem_u32(sm);
    const int t = threadIdx.x, lane = t & 31, w = t >> 5;
    const int m0 = blockIdx.y << 7, n0 = blockIdx.x << 6;
    const int z = blockIdx.z;
    const int K = Ee;
    const float* bias = z ? bg : bl;
    const char* Aph = (const char*)(Ah + (size_t)m0 * K);
    const char* Apl = (const char*)(Al + (size_t)m0 * K);
    const char* Bph = (const char*)((z ? g_B1gh : g_B1lh) + (size_t)n0 * K);
    const char* Bpl = (const char*)((z ? g_B1gl : g_B1ll) + (size_t)n0 * K);
    const size_t krow = (size_t)K * 2;
    const int KC = K >> 5;

    GEMM_CORE3()

    const int erow = m0 + w * 32 + (lane >> 2);
    const int ecol = n0 + ((lane & 3) << 1);
    #pragma unroll
    for (int nt = 0; nt < 8; nt++) {
        const int gn = ecol + nt * 8;
        const float2 bb2 = *(const float2*)(bias + gn);
        #pragma unroll
        for (int mt = 0; mt < 2; mt++) {
            #pragma unroll
            for (int half = 0; half < 2; half++) {
                const float v0 = acc[mt][nt][half * 2 + 0] + bb2.x;
                const float v1 = acc[mt][nt][half * 2 + 1] + bb2.y;
                const int gm = erow + mt * 16 + half * 8;
                if (z == 0) {
                    *(float2*)(g_qkv_l + (size_t)gm * QKVN + gn) = make_float2(v0, v1);
                } else if (n0 < 1024) {
                    float r0, r1;
                    const uint32_t hi = pack_bf2(v0, v1, r0, r1);
                    const uint32_t lo = pack_bf2n(r0, r1);
                    *(uint32_t*)(g_qk_h + (size_t)gm * 1024 + gn) = hi;
                    *(uint32_t*)(g_qk_l + (size_t)gm * 1024 + gn) = lo;
                } else {
                    *(float2*)(g_vg + (size_t)gm * Ee + (gn - 1024)) = make_float2(v0, v1);
                }
            }
        }
    }
}

// ---------------- elementwise hi/lo split ------------------------------------
__global__ void split2(const float* __restrict__ in,
                       __nv_bfloat16* __restrict__ oh, __nv_bfloat16* __restrict__ ol)
{
    const size_t i = ((size_t)blockIdx.x * 256 + threadIdx.x) << 2;
    const float4 v = *(const float4*)(in + i);
    float vv[4] = {v.x, v.y, v.z, v.w};
    union { __nv_bfloat16 b[4]; uint2 u; } hu, lu;
    #pragma unroll
    for (int j = 0; j < 4; j++) {
        hu.b[j] = __float2bfloat16(vv[j]);
        lu.b[j] = __float2bfloat16(vv[j] - __bfloat162float(hu.b[j]));
    }
    *(uint2*)(oh + i) = hu.u;
    *(uint2*)(ol + i) = lu.u;
}

// transpose + split V
__global__ void __launch_bounds__(256)
vt_split(const float* __restrict__ vg,
         __nv_bfloat16* __restrict__ vh, __nv_bfloat16* __restrict__ vl)
{
    __shared__ float tile[64][65];
    const int t = threadIdx.x;
    const int bh = blockIdx.y, b = bh >> 3, h = bh & 7;
    const int s0 = blockIdx.x << 6;
    #pragma unroll
    for (int i = 0; i < 4; i++) {
        const int idx = t + (i << 8);
        const int row = idx >> 4, c4 = (idx & 15) << 2;
        float4 v = *(const float4*)(vg + (size_t)(b * Ss + s0 + row) * Ee + h * 64 + c4);
        tile[row][c4] = v.x; tile[row][c4 + 1] = v.y;
        tile[row][c4 + 2] = v.z; tile[row][c4 + 3] = v.w;
    }
    __syncthreads();
    #pragma unroll
    for (int i = 0; i < 4; i++) {
        const int idx = t + (i << 8);
        const int d = idx >> 4, sc = (idx & 15) << 2;
        uint16_t hh[4], ll[4];
        #pragma unroll
        for (int k = 0; k < 4; k++) {
            const float f = tile[sc + k][d];
            __nv_bfloat16 hb = __float2bfloat16(f);
            const float lf = f - __bfloat162float(hb);
            __nv_bfloat16 lb = __float2bfloat16(lf);
            hh[k] = *(uint16_t*)&hb; ll[k] = *(uint16_t*)&lb;
        }
        uint2 hv = make_uint2((uint32_t)hh[0] | ((uint32_t)hh[1] << 16),
                              (uint32_t)hh[2] | ((uint32_t)hh[3] << 16));
        uint2 lv = make_uint2((uint32_t)ll[0] | ((uint32_t)ll[1] << 16),
                              (uint32_t)ll[2] | ((uint32_t)ll[3] << 16));
        *(uint2*)(vh + (size_t)(bh * 64 + d) * Ss + s0 + sc) = hv;
        *(uint2*)(vl + (size_t)(bh * 64 + d) * Ss + s0 + sc) = lv;
    }
}

// ---------------- flash attention: 128 threads, 64-query tiles ---------------
#define AT_SMEM 81920

#define S_TERM(AF, KB)                                                          \
    _Pragma("unroll")                                                           \
    for (int ks = 0; ks < 4; ks++) {                                            \
        uint32_t bfr[4][4];                                                     \
        _Pragma("unroll")                                                       \
        for (int n4 = 0; n4 < 4; n4++)                                          \
            ldsm4(bfr[n4], (KB) + sw128(((nrow + n4 * 16) << 7) + ks * 32 + bcb)); \
        _Pragma("unroll")                                                       \
        for (int nt = 0; nt < 8; nt++)                                          \
            mma16816(sA[nt], AF[ks],                                            \
                     bfr[nt >> 1][(nt & 1) * 2], bfr[nt >> 1][(nt & 1) * 2 + 1]); \
    }

__global__ void __launch_bounds__(128)
flash_attn(const __nv_bfloat16* __restrict__ qkh, const __nv_bfloat16* __restrict__ qkl,
           const __nv_bfloat16* __restrict__ vth, const __nv_bfloat16* __restrict__ vtl)
{
    extern __shared__ char sm[];
    const uint32_t sb = smem_u32(sm);
    const int t = threadIdx.x, lane = t & 31, w = t >> 5;
    const int bh = blockIdx.y, b = bh >> 3, h = bh & 7;
    const int q0 = blockIdx.x << 6;
    const uint32_t Qh = sb, Ql = sb + 8192;

    {
        const char* srch = (const char*)(qkh + (size_t)(b * Ss + q0) * 1024 + h * 64);
        const char* srcl = (const char*)(qkl + (size_t)(b * Ss + q0) * 1024 + h * 64);
        #pragma unroll
        for (int i = 0; i < 4; i++) {
            const int idx = t + (i << 7);
            const int row = idx >> 3, ch = (idx & 7) << 4;
            const uint32_t off = sw128((row << 7) | ch);
            cp16(Qh + off, srch + (size_t)row * 2048 + ch);
            cp16(Ql + off, srcl + (size_t)row * 2048 + ch);
        }
        asm volatile("cp.async.commit_group;" ::: "memory");
    }

    auto load_kv = [&](int kt, int buf) {
        const uint32_t bb = sb + 16384 + buf * 32768;
        const char* kh = (const char*)(qkh + (size_t)(b * Ss + kt * 64) * 1024 + 512 + h * 64);
        const char* kl = (const char*)(qkl + (size_t)(b * Ss + kt * 64) * 1024 + 512 + h * 64);
        const char* vh = (const char*)(vth + (size_t)(bh * 64) * Ss + kt * 64);
        const char* vl = (const char*)(vtl + (size_t)(bh * 64) * Ss + kt * 64);
        #pragma unroll
        for (int i = 0; i < 4; i++) {
            const int idx = t + (i << 7);
            const int row = idx >> 3, ch = (idx & 7) << 4;
            const uint32_t off = sw128((row << 7) | ch);
            cp16(bb + off,         kh + (size_t)row * 2048 + ch);
            cp16(bb + 8192 + off,  kl + (size_t)row * 2048 + ch);
            cp16(bb + 16384 + off, vh + (size_t)row * 2048 + ch);
            cp16(bb + 24576 + off, vl + (size_t)row * 2048 + ch);
        }
        asm volatile("cp.async.commit_group;" ::: "memory");
    };
    load_kv(0, 0);
    load_kv(1, 1);

    asm volatile("cp.async.wait_group 2;" ::: "memory");
    __syncthreads();

    const int arow = (w << 4) + (lane & 15);
    const int acb  = (lane >> 4) << 4;
    uint32_t qh[4][4], ql[4][4];
    #pragma unroll
    for (int ks = 0; ks < 4; ks++) {
        ldsm4(qh[ks], Qh + sw128((arow << 7) + ks * 32 + acb));
        ldsm4(ql[ks], Ql + sw128((arow << 7) + ks * 32 + acb));
    }

    const int nrow = ((lane >> 4) & 1) * 8 + (lane & 7);
    const int bcb  = ((lane >> 3) & 1) << 4;

    float o[8][4] = {};
    float m0 = -INFINITY, m1 = -INFINITY, l0 = 0.f, l1 = 0.f;

    for (int kt = 0; kt < 16; kt++) {
        const int buf = kt & 1;
        if (kt + 1 < 16) asm volatile("cp.async.wait_group 1;" ::: "memory");
        else             asm volatile("cp.async.wait_group 0;" ::: "memory");
        __syncthreads();
        const uint32_t Kh = sb + 16384 + buf * 32768;
        const uint32_t Kl = Kh + 8192, Vh = Kh + 16384, Vl = Kh + 24576;

        float sA[8][4] = {};
        S_TERM(qh, Kh)
        S_TERM(qh, Kl)
        S_TERM(ql, Kh)

        float rm0 = -INFINITY, rm1 = -INFINITY;
        #pragma unroll
        for (int nt = 0; nt < 8; nt++) {
            #pragma unroll
            for (int j = 0; j < 4; j++) sA[nt][j] *= 0.125f;
            rm0 = fmaxf(rm0, fmaxf(sA[nt][0], sA[nt][1]));
            rm1 = fmaxf(rm1, fmaxf(sA[nt][2], sA[nt][3]));
        }
        rm0 = fmaxf(rm0, __shfl_xor_sync(0xffffffffu, rm0, 1));
        rm0 = fmaxf(rm0, __shfl_xor_sync(0xffffffffu, rm0, 2));
        rm1 = fmaxf(rm1, __shfl_xor_sync(0xffffffffu, rm1, 1));
        rm1 = fmaxf(rm1, __shfl_xor_sync(0xffffffffu, rm1, 2));
        const float mn0 = fmaxf(m0, rm0), mn1 = fmaxf(m1, rm1);
        const float sc0 = __expf(m0 - mn0), sc1 = __expf(m1 - mn1);
        m0 = mn0; m1 = mn1;

        float ps0 = 0.f, ps1 = 0.f;
        uint32_t phi[4][4], plo[4][4];
        #pragma unroll
        for (int j = 0; j < 4; j++) {
            float p[2][4];
            #pragma unroll
            for (int e = 0; e < 2; e++) {
                p[e][0] = __expf(sA[2 * j + e][0] - mn0);
                p[e][1] = __expf(sA[2 * j + e][1] - mn0);
                p[e][2] = __expf(sA[2 * j + e][2] - mn1);
                p[e][3] = __expf(sA[2 * j + e][3] - mn1);
                ps0 += p[e][0] + p[e][1];
                ps1 += p[e][2] + p[e][3];
            }
            float r0, r1;
            phi[j][0] = pack_bf2(p[0][0], p[0][1], r0, r1); plo[j][0] = pack_bf2n(r0, r1);
            phi[j][1] = pack_bf2(p[0][2], p[0][3], r0, r1); plo[j][1] = pack_bf2n(r0, r1);
            phi[j][2] = pack_bf2(p[1][0], p[1][1], r0, r1); plo[j][2] = pack_bf2n(r0, r1);
            phi[j][3] = pack_bf2(p[1][2], p[1][3], r0, r1); plo[j][3] = pack_bf2n(r0, r1);
        }
        l0 = l0 * sc0 + ps0;
        l1 = l1 * sc1 + ps1;
        #pragma unroll
        for (int nt = 0; nt < 8; nt++) {
            o[nt][0] *= sc0; o[nt][1] *= sc0;
            o[nt][2] *= sc1; o[nt][3] *= sc1;
        }

        #pragma unroll
        for (int ks = 0; ks < 4; ks++) {
            uint32_t bv[4][4];
            #pragma unroll
            for (int n4 = 0; n4 < 4; n4++)
                ldsm4(bv[n4], Vh + sw128(((nrow + n4 * 16) << 7) + ks * 32 + bcb));
            #pragma unroll
            for (int nt = 0; nt < 8; nt++) {
                mma16816(o[nt], phi[ks], bv[nt >> 1][(nt & 1) * 2], bv[nt >> 1][(nt & 1) * 2 + 1]);
                mma16816(o[nt], plo[ks], bv[nt >> 1][(nt & 1) * 2], bv[nt >> 1][(nt & 1) * 2 + 1]);
            }
            #pragma unroll
            for (int n4 = 0; n4 < 4; n4++)
                ldsm4(bv[n4], Vl + sw128(((nrow + n4 * 16) << 7) + ks * 32 + bcb));
            #pragma unroll
            for (int nt = 0; nt < 8; nt++)
                mma16816(o[nt], phi[ks], bv[nt >> 1][(nt & 1) * 2], bv[nt >> 1][(nt & 1) * 2 + 1]);
        }
        __syncthreads();
        if (kt + 2 < 16) load_kv(kt + 2, buf);
    }

    l0 += __shfl_xor_sync(0xffffffffu, l0, 1);
    l0 += __shfl_xor_sync(0xffffffffu, l0, 2);
    l1 += __shfl_xor_sync(0xffffffffu, l1, 1);
    l1 += __shfl_xor_sync(0xffffffffu, l1, 2);
    const float i0 = 1.f / l0, i1 = 1.f / l1;
    const int r = lane >> 2, c2 = (lane & 3) << 1;
    const int row0 = b * Ss + q0 + (w << 4) + r;
    __nv_bfloat16* ha = g_A2h + (size_t)row0 * 1024;
    __nv_bfloat16* la = g_A2l + (size_t)row0 * 1024;
    __nv_bfloat16* hb2 = g_A2h + (size_t)(row0 + 8) * 1024;
    __nv_bfloat16* lb2 = g_A2l + (size_t)(row0 + 8) * 1024;
    #pragma unroll
    for (int nt = 0; nt < 8; nt++) {
        const int col = 512 + h * 64 + nt * 8 + c2;
        float r0, r1;
        uint32_t hi = pack_bf2(o[nt][0] * i0, o[nt][1] * i0, r0, r1);
        uint32_t lo = pack_bf2n(r0, r1);
        *(uint32_t*)(ha + col) = hi;
        *(uint32_t*)(la + col) = lo;
        hi = pack_bf2(o[nt][2] * i1, o[nt][3] * i1, r0, r1);
        lo = pack_bf2n(r0, r1);
        *(uint32_t*)(hb2 + col) = hi;
        *(uint32_t*)(lb2 + col) = lo;
    }
}

// ---------------- fp32 SIMT GEMM for Wc (double-buffered) --------------------
__global__ void __launch_bounds__(256)
wc_gemm(const float* __restrict__ Wf, const float* __restrict__ Wl_out,
        const float* __restrict__ Wg_out, float* __restrict__ Wc)
{
    __shared__ float As[2][16][68];
    __shared__ float Bs[2][16][68];
    const int g = blockIdx.z;
    const float* A = Wf + (g ? Ee : 0);
    const float* W = g ? Wg_out : Wl_out;
    float* C = Wc + (g ? Ee : 0);
    const int t = threadIdx.x, tx = t & 15, ty = t >> 4;
    const int m0 = blockIdx.y * 64, n0 = blockIdx.x * 64;
    const int lr = t >> 2, lk = (t & 3) << 2;
    const int bkk = t >> 4, bcc = (t & 15) << 2;
    float acc[4][4] = {};

    float4 va = *(const float4*)(A + (size_t)(m0 + lr) * (2 * Ee) + lk);
    float4 vb = *(const float4*)(W + (size_t)bkk * Ee + n0 + bcc);
    int buf = 0;
    for (int k0 = 0; k0 < Ee; k0 += 16) {
        As[buf][lk + 0][lr] = va.x; As[buf][lk + 1][lr] = va.y;
        As[buf][lk + 2][lr] = va.z; As[buf][lk + 3][lr] = va.w;
        *(float4*)&Bs[buf][bkk][bcc] = vb;
        __syncthreads();
        if (k0 + 16 < Ee) {
            va = *(const float4*)(A + (size_t)(m0 + lr) * (2 * Ee) + k0 + 16 + lk);
            vb = *(const float4*)(W + (size_t)(k0 + 16 + bkk) * Ee + n0 + bcc);
        }
        #pragma unroll
        for (int kk = 0; kk < 16; kk++) {
            float4 a = *(const float4*)&As[buf][kk][ty << 2];
            float4 b = *(const float4*)&Bs[buf][kk][tx << 2];
            float av[4] = {a.x, a.y, a.z, a.w};
            float bv[4] = {b.x, b.y, b.z, b.w};
            #pragma unroll
            for (int i = 0; i < 4; i++)
                #pragma unroll
                for (int j = 0; j < 4; j++)
                    acc[i][j] = fmaf(av[i], bv[j], acc[i][j]);
        }
        buf ^= 1;
    }
    #pragma unroll
    for (int i = 0; i < 4; i++)
        *(float4*)(C + (size_t)(m0 + (ty << 2) + i) * (2 * Ee) + n0 + (tx << 2)) =
            make_float4(acc[i][0], acc[i][1], acc[i][2], acc[i][3]);
}

// ---------------- combined bias ----------------------------------------------
__global__ void __launch_bounds__(128)
bias_combine_kernel(const float* __restrict__ Wf,
                    const float* __restrict__ bl,
                    const float* __restrict__ bg,
                    const float* __restrict__ bf)
{
    const int o = blockIdx.x;
    const int t = threadIdx.x;
    const float* row = Wf + (size_t)o * (2 * Ee);
    float acc = 0.f;
    for (int j = t; j < Ee; j += 128)
        acc += row[j] * bl[j] + row[Ee + j] * bg[j];
    #pragma unroll
    for (int off = 16; off; off >>= 1)
        acc += __shfl_xor_sync(0xffffffffu, acc, off);
    __shared__ float ws[4];
    if ((t & 31) == 0) ws[t >> 5] = acc;
    __syncthreads();
    if (t == 0) g_bc[o] = ws[0] + ws[1] + ws[2] + ws[3] + bf[o];
}

// ---------------- local (banded) attention -> A2 hi/lo (round-11 version) ----
__global__ void __launch_bounds__(256)
local_attn_kernel(const float* __restrict__ qkv)
{
    const int warp = (blockIdx.x * blockDim.x + threadIdx.x) >> 5;
    const int lane = threadIdx.x & 31;
    const int q  = warp & (Ss - 1);
    const int bh = warp >> 10;
    const int b  = bh >> 3, h = bh & 7;

    const float* base = qkv + (size_t)(b * Ss) * QKVN + h * DHd;
    const float* qrow = base + (size_t)q * QKVN;
    const float q0 = qrow[lane], q1 = qrow[lane + 32];

    float s[7];
    float mmax = -1e30f;
    #pragma unroll
    for (int jj = 0; jj < 7; jj++) {
        const int j = q - LOCALW + jj;
        const bool valid = (j >= 0) && (j < Ss);
        float d = 0.f;
        if (valid) {
            const float* krow = base + (size_t)j * QKVN + Ee;
            d = q0 * krow[lane] + q1 * krow[lane + 32];
        }
        #pragma unroll
        for (int off = 16; off; off >>= 1)
            d += __shfl_xor_sync(0xffffffffu, d, off);
        d = valid ? d * 0.125f : -1e30f;
        s[jj] = d;
        mmax = fmaxf(mmax, d);
    }
    float sum = 0.f;
    #pragma unroll
    for (int jj = 0; jj < 7; jj++) { s[jj] = __expf(s[jj] - mmax); sum += s[jj]; }
    const float inv = 1.f / sum;
    float o0 = 0.f, o1 = 0.f;
    #pragma unroll
    for (int jj = 0; jj < 7; jj++) {
        const int j = q - LOCALW + jj;
        if (j >= 0 && j < Ss) {
            const float* vrow = base + (size_t)j * QKVN + 2 * Ee;
            o0 = fmaf(s[jj], vrow[lane],      o0);
            o1 = fmaf(s[jj], vrow[lane + 32], o1);
        }
    }
    const float v0 = o0 * inv, v1 = o1 * inv;
    const float p0 = __shfl_down_sync(0xffffffffu, v0, 1);
    const float p1 = __shfl_down_sync(0xffffffffu, v1, 1);
    if (!(lane & 1)) {
        __nv_bfloat16* a2h = g_A2h + (size_t)(b * Ss + q) * 1024;
        __nv_bfloat16* a2l = g_A2l + (size_t)(b * Ss + q) * 1024;
        const int c0 = h * DHd + lane;
        float r0, r1;
        uint32_t hi = pack_bf2(v0, p0, r0, r1);
        uint32_t lo = pack_bf2n(r0, r1);
        *(uint32_t*)(a2h + c0) = hi;
        *(uint32_t*)(a2l + c0) = lo;
        hi = pack_bf2(v1, p1, r0, r1);
        lo = pack_bf2n(r0, r1);
        *(uint32_t*)(a2h + c0 + 32) = hi;
        *(uint32_t*)(a2l + c0 + 32) = lo;
    }
}

// ---------------- launcher -----------------------------------------------------
extern "C" void kernel_launch(void* const* d_in, const int* in_sizes, int n_in,
                              void* d_out, int out_size)
{
    (void)in_sizes; (void)n_in; (void)out_size;
    const float* x      = (const float*)d_in[0];
    const float* Wl_in  = (const float*)d_in[1];
    const float* bl_in  = (const float*)d_in[2];
    const float* Wl_out = (const float*)d_in[3];
    const float* bl_out = (const float*)d_in[4];
    const float* Wg_in  = (const float*)d_in[5];
    const float* bg_in  = (const float*)d_in[6];
    const float* Wg_out = (const float*)d_in[7];
    const float* bg_out = (const float*)d_in[8];
    const float* Wf     = (const float*)d_in[9];
    const float* bf     = (const float*)d_in[10];
    float* out = (float*)d_out;

    float *qkv_l, *vg, *Wc, *bc;
    __nv_bfloat16 *A1h, *A1l, *A2h, *A2l, *B2h, *B2l, *qkh, *qkl, *vth, *vtl;
    __nv_bfloat16 *B1lh, *B1ll, *B1gh, *B1gl;
    cudaGetSymbolAddress((void**)&qkv_l, g_qkv_l);
    cudaGetSymbolAddress((void**)&vg,    g_vg);
    cudaGetSymbolAddress((void**)&Wc,    g_Wc);
    cudaGetSymbolAddress((void**)&bc,    g_bc);
    cudaGetSymbolAddress((void**)&A1h,   g_A1h);
    cudaGetSymbolAddress((void**)&A1l,   g_A1l);
    cudaGetSymbolAddress((void**)&B1lh,  g_B1lh);
    cudaGetSymbolAddress((void**)&B1ll,  g_B1ll);
    cudaGetSymbolAddress((void**)&B1gh,  g_B1gh);
    cudaGetSymbolAddress((void**)&B1gl,  g_B1gl);
    cudaGetSymbolAddress((void**)&A2h,   g_A2h);
    cudaGetSymbolAddress((void**)&A2l,   g_A2l);
    cudaGetSymbolAddress((void**)&B2h,   g_B2h);
    cudaGetSymbolAddress((void**)&B2l,   g_B2l);
    cudaGetSymbolAddress((void**)&qkh,   g_qk_h);
    cudaGetSymbolAddress((void**)&qkl,   g_qk_l);
    cudaGetSymbolAddress((void**)&vth,   g_vt_h);
    cudaGetSymbolAddress((void**)&vtl,   g_vt_l);

    cudaFuncSetAttribute(mma_gemm3,
                         cudaFuncAttributeMaxDynamicSharedMemorySize, MMA_SMEM3);
    cudaFuncSetAttribute(qkv_fused,
                         cudaFuncAttributeMaxDynamicSharedMemorySize, MMA_SMEM3);
    cudaFuncSetAttribute(flash_attn,
                         cudaFuncAttributeMaxDynamicSharedMemorySize, AT_SMEM);

    // 1) hi/lo splits of x and input-proj weights (round-11 structure)
    split2<<<(Mm * Ee) / 1024, 256>>>(x, A1h, A1l);
    split2<<<(QKVN * Ee) / 1024, 256>>>(Wl_in, B1lh, B1ll);
    split2<<<(QKVN * Ee) / 1024, 256>>>(Wg_in, B1gh, B1gl);

    // 2) combined epilogue weights + bias, then split
    wc_gemm<<<dim3(8, 8, 2), 256>>>(Wf, Wl_out, Wg_out, Wc);
    bias_combine_kernel<<<Ee, 128>>>(Wf, bl_out, bg_out, bf);
    split2<<<(Ee * 2 * Ee) / 1024, 256>>>(Wc, B2h, B2l);

    // 3) fused QKV projections (4-stage single-sync core — the one change)
    qkv_fused<<<dim3(QKVN / 64, Mm / 128, 2), 128, MMA_SMEM3>>>(
        A1h, A1l, bl_in, bg_in);

    // 4) local attention -> A2 (per-warp, round-11 version)
    local_attn_kernel<<<(Bb * Hh * Ss) / 8, 256>>>(qkv_l);

    // 5) V transpose-split, flash attention
    vt_split<<<dim3(Ss / 64, Bb * Hh), 256>>>(vg, vth, vtl);
    flash_attn<<<dim3(Ss / 64, Bb * Hh), 128, AT_SMEM>>>(qkh, qkl, vth, vtl);

    // 6) final fused projection + ReLU
    mma_gemm3<<<dim3(Ee / 64, Mm / 128), 128, MMA_SMEM3>>>(
        A2h, A2l, B2h, B2l, bc, out, 1024, Ee);
}

// round 16
// speedup vs baseline: 1.1274x; 1.0775x over previous
#include <cuda_runtime.h>
#include <cuda_bf16.h>
#include <math.h>
#include <stdint.h>

// Problem constants
#define Bb   8
#define Ss   1024
#define Ee   512
#define Hh   8
#define DHd  64
#define Mm   (Bb * Ss)        // 8192
#define QKVN (3 * Ee)         // 1536
#define LOCALW 3

// ---------------- scratch (device globals) ----------------------------------
__device__ float g_qkv_l[(size_t)Mm * QKVN];
__device__ float g_vg   [(size_t)Mm * Ee];
__device__ float g_Wc   [(size_t)Ee * 2 * Ee];
__device__ float g_bc   [Ee];
__device__ __nv_bfloat16 g_A1h[(size_t)Mm * Ee];
__device__ __nv_bfloat16 g_A1l[(size_t)Mm * Ee];
__device__ __nv_bfloat16 g_B1lh[(size_t)QKVN * Ee];
__device__ __nv_bfloat16 g_B1ll[(size_t)QKVN * Ee];
__device__ __nv_bfloat16 g_B1gh[(size_t)QKVN * Ee];
__device__ __nv_bfloat16 g_B1gl[(size_t)QKVN * Ee];
__device__ __nv_bfloat16 g_A2h[(size_t)Mm * 1024];
__device__ __nv_bfloat16 g_A2l[(size_t)Mm * 1024];
__device__ __nv_bfloat16 g_B2h[(size_t)Ee * 1024];
__device__ __nv_bfloat16 g_B2l[(size_t)Ee * 1024];
__device__ __nv_bfloat16 g_qk_h[(size_t)Mm * 1024];
__device__ __nv_bfloat16 g_qk_l[(size_t)Mm * 1024];
__device__ __nv_bfloat16 g_vt_h[(size_t)64 * 64 * Ss];
__device__ __nv_bfloat16 g_vt_l[(size_t)64 * 64 * Ss];

// ---------------- PTX helpers (base ISA only) --------------------------------
__device__ __forceinline__ uint32_t smem_u32(const void* p) {
    uint32_t a;
    asm("{ .reg .u64 t; cvta.to.shared.u64 t, %1; cvt.u32.u64 %0, t; }"
        : "=r"(a) : "l"(p));
    return a;
}
__device__ __forceinline__ uint32_t sw128(uint32_t o) { return o ^ ((o >> 3) & 0x70); }
__device__ __forceinline__ uint32_t sw64(uint32_t o)  { return o ^ ((o >> 3) & 0x30); }

__device__ __forceinline__ void cp16(uint32_t dst, const void* src) {
    asm volatile("cp.async.cg.shared.global [%0], [%1], 16;"
                 :: "r"(dst), "l"(src) : "memory");
}
__device__ __forceinline__ void ldsm4(uint32_t* d, uint32_t a) {
    asm volatile("ldmatrix.sync.aligned.m8n8.x4.shared.b16 {%0,%1,%2,%3}, [%4];"
                 : "=r"(d[0]), "=r"(d[1]), "=r"(d[2]), "=r"(d[3]) : "r"(a));
}
__device__ __forceinline__ void mma16816(float* c, const uint32_t* a,
                                         uint32_t b0, uint32_t b1) {
    asm volatile("mma.sync.aligned.m16n8k16.row.col.f32.bf16.bf16.f32 "
                 "{%0,%1,%2,%3}, {%4,%5,%6,%7}, {%8,%9}, {%0,%1,%2,%3};"
                 : "+f"(c[0]), "+f"(c[1]), "+f"(c[2]), "+f"(c[3])
                 : "r"(a[0]), "r"(a[1]), "r"(a[2]), "r"(a[3]), "r"(b0), "r"(b1));
}
__device__ __forceinline__ uint32_t pack_bf2(float a, float b, float& ra, float& rb) {
    __nv_bfloat16 ha = __float2bfloat16(a), hb = __float2bfloat16(b);
    ra = a - __bfloat162float(ha);
    rb = b - __bfloat162float(hb);
    return ((uint32_t)*(uint16_t*)&hb << 16) | (uint32_t)*(uint16_t*)&ha;
}
__device__ __forceinline__ uint32_t pack_bf2n(float a, float b) {
    __nv_bfloat16 ha = __float2bfloat16(a), hb = __float2bfloat16(b);
    return ((uint32_t)*(uint16_t*)&hb << 16) | (uint32_t)*(uint16_t*)&ha;
}

// ======== 3-term hi/lo GEMM core: 128 thr, tile 128Mx64N, K-chunk 32 =========
// Round-11 proven core: 3 stages x 24KB = 72KB -> 3 CTA/SM, two syncs/chunk.
#define MMA_SMEM3 73728

#define GEMM_CORE3()                                                            \
    auto load_stage = [&](int c, int sbuf) {                                    \
        const uint32_t st = sbase + sbuf * 24576;                               \
        const size_t cb = (size_t)c * 64;                                       \
        _Pragma("unroll")                                                       \
        for (int i = 0; i < 4; i++) {                                           \
            const int idx = t + (i << 7);                                       \
            const int row = idx >> 2;                                           \
            const int sc  = (idx & 3) << 4;                                     \
            const uint32_t off = sw64((row << 6) + sc);                         \
            const size_t go = (size_t)row * krow + cb + sc;                     \
            cp16(st + off,        Aph + go);                                    \
            cp16(st + 8192 + off, Apl + go);                                    \
        }                                                                       \
        _Pragma("unroll")                                                       \
        for (int i = 0; i < 2; i++) {                                           \
            const int idx = t + (i << 7);                                       \
            const int row = idx >> 2;                                           \
            const int sc  = (idx & 3) << 4;                                     \
            const uint32_t off = sw64((row << 6) + sc);                         \
            const size_t go = (size_t)row * krow + cb + sc;                     \
            cp16(st + 16384 + off, Bph + go);                                   \
            cp16(st + 20480 + off, Bpl + go);                                   \
        }                                                                       \
        asm volatile("cp.async.commit_group;" ::: "memory");                    \
    };                                                                          \
    load_stage(0, 0); load_stage(1, 1); load_stage(2, 2);                       \
    float acc[2][8][4] = {};                                                    \
    const int arow0 = w * 32 + (lane & 15);                                     \
    const int acb   = (lane >> 4) << 4;                                         \
    const int nrow0 = ((lane >> 4) & 1) * 8 + (lane & 7);                       \
    const int bcb   = ((lane >> 3) & 1) << 4;                                   \
    int buf = 0;                                                                \
    for (int c = 0; c < KC; c++) {                                              \
        if (c + 2 < KC)      asm volatile("cp.async.wait_group 2;" ::: "memory"); \
        else if (c + 1 < KC) asm volatile("cp.async.wait_group 1;" ::: "memory"); \
        else                 asm volatile("cp.async.wait_group 0;" ::: "memory"); \
        __syncthreads();                                                        \
        const uint32_t sAh = sbase + buf * 24576;                               \
        const uint32_t sAl = sAh + 8192;                                        \
        const uint32_t sBh = sAh + 16384;                                       \
        const uint32_t sBl = sAh + 20480;                                       \
        _Pragma("unroll")                                                       \
        for (int ks = 0; ks < 2; ks++) {                                        \
            uint32_t ah[2][4], al[2][4];                                        \
            _Pragma("unroll")                                                   \
            for (int mt = 0; mt < 2; mt++) {                                    \
                const uint32_t ro = sw64(((arow0 + mt * 16) << 6) + ks * 32 + acb); \
                ldsm4(ah[mt], sAh + ro);                                        \
                ldsm4(al[mt], sAl + ro);                                        \
            }                                                                   \
            uint32_t bh[4][4], bl_[4][4];                                       \
            _Pragma("unroll")                                                   \
            for (int n4 = 0; n4 < 4; n4++) {                                    \
                const uint32_t ro = sw64(((nrow0 + n4 * 16) << 6) + ks * 32 + bcb); \
                ldsm4(bh[n4], sBh + ro);                                        \
                ldsm4(bl_[n4], sBl + ro);                                       \
            }                                                                   \
            _Pragma("unroll")                                                   \
            for (int mt = 0; mt < 2; mt++)                                      \
                _Pragma("unroll")                                               \
                for (int nt = 0; nt < 8; nt++) {                                \
                    const uint32_t h0 = bh[nt >> 1][(nt & 1) * 2];              \
                    const uint32_t h1 = bh[nt >> 1][(nt & 1) * 2 + 1];          \
                    mma16816(acc[mt][nt], ah[mt], h0, h1);                      \
                    mma16816(acc[mt][nt], al[mt], h0, h1);                      \
                    mma16816(acc[mt][nt], ah[mt],                               \
                             bl_[nt >> 1][(nt & 1) * 2], bl_[nt >> 1][(nt & 1) * 2 + 1]); \
                }                                                               \
        }                                                                       \
        __syncthreads();                                                        \
        if (c + 3 < KC) load_stage(c + 3, buf);                                 \
        buf = (buf == 2) ? 0 : buf + 1;                                         \
    }

// ---------------- final GEMM: out = relu(A2 @ B2^T + bc) --------------------
__global__ void __launch_bounds__(128)
mma_gemm3(const __nv_bfloat16* __restrict__ Ah, const __nv_bfloat16* __restrict__ Al,
          const __nv_bfloat16* __restrict__ Bh, const __nv_bfloat16* __restrict__ Bl,
          const float* __restrict__ bias, float* __restrict__ C, int K, int ldc)
{
    extern __shared__ char sm[];
    const uint32_t sbase = smem_u32(sm);
    const int t = threadIdx.x, lane = t & 31, w = t >> 5;
    const int m0 = blockIdx.y << 7, n0 = blockIdx.x << 6;
    const char* Aph = (const char*)(Ah + (size_t)m0 * K);
    const char* Apl = (const char*)(Al + (size_t)m0 * K);
    const char* Bph = (const char*)(Bh + (size_t)n0 * K);
    const char* Bpl = (const char*)(Bl + (size_t)n0 * K);
    const size_t krow = (size_t)K * 2;
    const int KC = K >> 5;

    GEMM_CORE3()

    const int erow = m0 + w * 32 + (lane >> 2);
    const int ecol = n0 + ((lane & 3) << 1);
    #pragma unroll
    for (int nt = 0; nt < 8; nt++) {
        const int gn = ecol + nt * 8;
        const float2 bb2 = *(const float2*)(bias + gn);
        #pragma unroll
        for (int mt = 0; mt < 2; mt++) {
            #pragma unroll
            for (int half = 0; half < 2; half++) {
                float v0 = fmaxf(acc[mt][nt][half * 2 + 0] + bb2.x, 0.f);
                float v1 = fmaxf(acc[mt][nt][half * 2 + 1] + bb2.y, 0.f);
                const int gm = erow + mt * 16 + half * 8;
                *(float2*)(C + (size_t)gm * ldc + gn) = make_float2(v0, v1);
            }
        }
    }
}

// ---------------- fused QKV GEMM (both blocks via blockIdx.z) ----------------
__global__ void __launch_bounds__(128)
qkv_fused(const __nv_bfloat16* __restrict__ Ah, const __nv_bfloat16* __restrict__ Al,
          const float* __restrict__ bl, const float* __restrict__ bg)
{
    extern __shared__ char sm[];
    const uint32_t sbase = smem_u32(sm);
    const int t = threadIdx.x, lane = t & 31, w = t >> 5;
    const int m0 = blockIdx.y << 7, n0 = blockIdx.x << 6;
    const int z = blockIdx.z;
    const int K = Ee;
    const float* bias = z ? bg : bl;
    const char* Aph = (const char*)(Ah + (size_t)m0 * K);
    const char* Apl = (const char*)(Al + (size_t)m0 * K);
    const char* Bph = (const char*)((z ? g_B1gh : g_B1lh) + (size_t)n0 * K);
    const char* Bpl = (const char*)((z ? g_B1gl : g_B1ll) + (size_t)n0 * K);
    const size_t krow = (size_t)K * 2;
    const int KC = K >> 5;

    GEMM_CORE3()

    const int erow = m0 + w * 32 + (lane >> 2);
    const int ecol = n0 + ((lane & 3) << 1);
    #pragma unroll
    for (int nt = 0; nt < 8; nt++) {
        const int gn = ecol + nt * 8;
        const float2 bb2 = *(const float2*)(bias + gn);
        #pragma unroll
        for (int mt = 0; mt < 2; mt++) {
            #pragma unroll
            for (int half = 0; half < 2; half++) {
                const float v0 = acc[mt][nt][half * 2 + 0] + bb2.x;
                const float v1 = acc[mt][nt][half * 2 + 1] + bb2.y;
                const int gm = erow + mt * 16 + half * 8;
                if (z == 0) {
                    *(float2*)(g_qkv_l + (size_t)gm * QKVN + gn) = make_float2(v0, v1);
                } else if (n0 < 1024) {
                    float r0, r1;
                    const uint32_t hi = pack_bf2(v0, v1, r0, r1);
                    const uint32_t lo = pack_bf2n(r0, r1);
                    *(uint32_t*)(g_qk_h + (size_t)gm * 1024 + gn) = hi;
                    *(uint32_t*)(g_qk_l + (size_t)gm * 1024 + gn) = lo;
                } else {
                    *(float2*)(g_vg + (size_t)gm * Ee + (gn - 1024)) = make_float2(v0, v1);
                }
            }
        }
    }
}

// ---------------- elementwise hi/lo split ------------------------------------
__global__ void split2(const float* __restrict__ in,
                       __nv_bfloat16* __restrict__ oh, __nv_bfloat16* __restrict__ ol)
{
    const size_t i = ((size_t)blockIdx.x * 256 + threadIdx.x) << 2;
    const float4 v = *(const float4*)(in + i);
    float vv[4] = {v.x, v.y, v.z, v.w};
    union { __nv_bfloat16 b[4]; uint2 u; } hu, lu;
    #pragma unroll
    for (int j = 0; j < 4; j++) {
        hu.b[j] = __float2bfloat16(vv[j]);
        lu.b[j] = __float2bfloat16(vv[j] - __bfloat162float(hu.b[j]));
    }
    *(uint2*)(oh + i) = hu.u;
    *(uint2*)(ol + i) = lu.u;
}

// transpose + split V
__global__ void __launch_bounds__(256)
vt_split(const float* __restrict__ vg,
         __nv_bfloat16* __restrict__ vh, __nv_bfloat16* __restrict__ vl)
{
    __shared__ float tile[64][65];
    const int t = threadIdx.x;
    const int bh = blockIdx.y, b = bh >> 3, h = bh & 7;
    const int s0 = blockIdx.x << 6;
    #pragma unroll
    for (int i = 0; i < 4; i++) {
        const int idx = t + (i << 8);
        const int row = idx >> 4, c4 = (idx & 15) << 2;
        float4 v = *(const float4*)(vg + (size_t)(b * Ss + s0 + row) * Ee + h * 64 + c4);
        tile[row][c4] = v.x; tile[row][c4 + 1] = v.y;
        tile[row][c4 + 2] = v.z; tile[row][c4 + 3] = v.w;
    }
    __syncthreads();
    #pragma unroll
    for (int i = 0; i < 4; i++) {
        const int idx = t + (i << 8);
        const int d = idx >> 4, sc = (idx & 15) << 2;
        uint16_t hh[4], ll[4];
        #pragma unroll
        for (int k = 0; k < 4; k++) {
            const float f = tile[sc + k][d];
            __nv_bfloat16 hb = __float2bfloat16(f);
            const float lf = f - __bfloat162float(hb);
            __nv_bfloat16 lb = __float2bfloat16(lf);
            hh[k] = *(uint16_t*)&hb; ll[k] = *(uint16_t*)&lb;
        }
        uint2 hv = make_uint2((uint32_t)hh[0] | ((uint32_t)hh[1] << 16),
                              (uint32_t)hh[2] | ((uint32_t)hh[3] << 16));
        uint2 lv = make_uint2((uint32_t)ll[0] | ((uint32_t)ll[1] << 16),
                              (uint32_t)ll[2] | ((uint32_t)ll[3] << 16));
        *(uint2*)(vh + (size_t)(bh * 64 + d) * Ss + s0 + sc) = hv;
        *(uint2*)(vl + (size_t)(bh * 64 + d) * Ss + s0 + sc) = lv;
    }
}

// ---------------- flash attention: 128 threads, 64-query tiles ---------------
#define AT_SMEM 81920

#define S_TERM(AF, KB)                                                          \
    _Pragma("unroll")                                                           \
    for (int ks = 0; ks < 4; ks++) {                                            \
        uint32_t bfr[4][4];                                                     \
        _Pragma("unroll")                                                       \
        for (int n4 = 0; n4 < 4; n4++)                                          \
            ldsm4(bfr[n4], (KB) + sw128(((nrow + n4 * 16) << 7) + ks * 32 + bcb)); \
        _Pragma("unroll")                                                       \
        for (int nt = 0; nt < 8; nt++)                                          \
            mma16816(sA[nt], AF[ks],                                            \
                     bfr[nt >> 1][(nt & 1) * 2], bfr[nt >> 1][(nt & 1) * 2 + 1]); \
    }

__global__ void __launch_bounds__(128)
flash_attn(const __nv_bfloat16* __restrict__ qkh, const __nv_bfloat16* __restrict__ qkl,
           const __nv_bfloat16* __restrict__ vth, const __nv_bfloat16* __restrict__ vtl)
{
    extern __shared__ char sm[];
    const uint32_t sb = smem_u32(sm);
    const int t = threadIdx.x, lane = t & 31, w = t >> 5;
    const int bh = blockIdx.y, b = bh >> 3, h = bh & 7;
    const int q0 = blockIdx.x << 6;
    const uint32_t Qh = sb, Ql = sb + 8192;

    {
        const char* srch = (const char*)(qkh + (size_t)(b * Ss + q0) * 1024 + h * 64);
        const char* srcl = (const char*)(qkl + (size_t)(b * Ss + q0) * 1024 + h * 64);
        #pragma unroll
        for (int i = 0; i < 4; i++) {
            const int idx = t + (i << 7);
            const int row = idx >> 3, ch = (idx & 7) << 4;
            const uint32_t off = sw128((row << 7) | ch);
            cp16(Qh + off, srch + (size_t)row * 2048 + ch);
            cp16(Ql + off, srcl + (size_t)row * 2048 + ch);
        }
        asm volatile("cp.async.commit_group;" ::: "memory");
    }

    auto load_kv = [&](int kt, int buf) {
        const uint32_t bb = sb + 16384 + buf * 32768;
        const char* kh = (const char*)(qkh + (size_t)(b * Ss + kt * 64) * 1024 + 512 + h * 64);
        const char* kl = (const char*)(qkl + (size_t)(b * Ss + kt * 64) * 1024 + 512 + h * 64);
        const char* vh = (const char*)(vth + (size_t)(bh * 64) * Ss + kt * 64);
        const char* vl = (const char*)(vtl + (size_t)(bh * 64) * Ss + kt * 64);
        #pragma unroll
        for (int i = 0; i < 4; i++) {
            const int idx = t + (i << 7);
            const int row = idx >> 3, ch = (idx & 7) << 4;
            const uint32_t off = sw128((row << 7) | ch);
            cp16(bb + off,         kh + (size_t)row * 2048 + ch);
            cp16(bb + 8192 + off,  kl + (size_t)row * 2048 + ch);
            cp16(bb + 16384 + off, vh + (size_t)row * 2048 + ch);
            cp16(bb + 24576 + off, vl + (size_t)row * 2048 + ch);
        }
        asm volatile("cp.async.commit_group;" ::: "memory");
    };
    load_kv(0, 0);
    load_kv(1, 1);

    asm volatile("cp.async.wait_group 2;" ::: "memory");
    __syncthreads();

    const int arow = (w << 4) + (lane & 15);
    const int acb  = (lane >> 4) << 4;
    uint32_t qh[4][4], ql[4][4];
    #pragma unroll
    for (int ks = 0; ks < 4; ks++) {
        ldsm4(qh[ks], Qh + sw128((arow << 7) + ks * 32 + acb));
        ldsm4(ql[ks], Ql + sw128((arow << 7) + ks * 32 + acb));
    }

    const int nrow = ((lane >> 4) & 1) * 8 + (lane & 7);
    const int bcb  = ((lane >> 3) & 1) << 4;

    float o[8][4] = {};
    float m0 = -INFINITY, m1 = -INFINITY, l0 = 0.f, l1 = 0.f;

    for (int kt = 0; kt < 16; kt++) {
        const int buf = kt & 1;
        if (kt + 1 < 16) asm volatile("cp.async.wait_group 1;" ::: "memory");
        else             asm volatile("cp.async.wait_group 0;" ::: "memory");
        __syncthreads();
        const uint32_t Kh = sb + 16384 + buf * 32768;
        const uint32_t Kl = Kh + 8192, Vh = Kh + 16384, Vl = Kh + 24576;

        float sA[8][4] = {};
        S_TERM(qh, Kh)
        S_TERM(qh, Kl)
        S_TERM(ql, Kh)

        float rm0 = -INFINITY, rm1 = -INFINITY;
        #pragma unroll
        for (int nt = 0; nt < 8; nt++) {
            #pragma unroll
            for (int j = 0; j < 4; j++) sA[nt][j] *= 0.125f;
            rm0 = fmaxf(rm0, fmaxf(sA[nt][0], sA[nt][1]));
            rm1 = fmaxf(rm1, fmaxf(sA[nt][2], sA[nt][3]));
        }
        rm0 = fmaxf(rm0, __shfl_xor_sync(0xffffffffu, rm0, 1));
        rm0 = fmaxf(rm0, __shfl_xor_sync(0xffffffffu, rm0, 2));
        rm1 = fmaxf(rm1, __shfl_xor_sync(0xffffffffu, rm1, 1));
        rm1 = fmaxf(rm1, __shfl_xor_sync(0xffffffffu, rm1, 2));
        const float mn0 = fmaxf(m0, rm0), mn1 = fmaxf(m1, rm1);
        const float sc0 = __expf(m0 - mn0), sc1 = __expf(m1 - mn1);
        m0 = mn0; m1 = mn1;

        float ps0 = 0.f, ps1 = 0.f;
        uint32_t phi[4][4], plo[4][4];
        #pragma unroll
        for (int j = 0; j < 4; j++) {
            float p[2][4];
            #pragma unroll
            for (int e = 0; e < 2; e++) {
                p[e][0] = __expf(sA[2 * j + e][0] - mn0);
                p[e][1] = __expf(sA[2 * j + e][1] - mn0);
                p[e][2] = __expf(sA[2 * j + e][2] - mn1);
                p[e][3] = __expf(sA[2 * j + e][3] - mn1);
                ps0 += p[e][0] + p[e][1];
                ps1 += p[e][2] + p[e][3];
            }
            float r0, r1;
            phi[j][0] = pack_bf2(p[0][0], p[0][1], r0, r1); plo[j][0] = pack_bf2n(r0, r1);
            phi[j][1] = pack_bf2(p[0][2], p[0][3], r0, r1); plo[j][1] = pack_bf2n(r0, r1);
            phi[j][2] = pack_bf2(p[1][0], p[1][1], r0, r1); plo[j][2] = pack_bf2n(r0, r1);
            phi[j][3] = pack_bf2(p[1][2], p[1][3], r0, r1); plo[j][3] = pack_bf2n(r0, r1);
        }
        l0 = l0 * sc0 + ps0;
        l1 = l1 * sc1 + ps1;
        #pragma unroll
        for (int nt = 0; nt < 8; nt++) {
            o[nt][0] *= sc0; o[nt][1] *= sc0;
            o[nt][2] *= sc1; o[nt][3] *= sc1;
        }

        #pragma unroll
        for (int ks = 0; ks < 4; ks++) {
            uint32_t bv[4][4];
            #pragma unroll
            for (int n4 = 0; n4 < 4; n4++)
                ldsm4(bv[n4], Vh + sw128(((nrow + n4 * 16) << 7) + ks * 32 + bcb));
            #pragma unroll
            for (int nt = 0; nt < 8; nt++) {
                mma16816(o[nt], phi[ks], bv[nt >> 1][(nt & 1) * 2], bv[nt >> 1][(nt & 1) * 2 + 1]);
                mma16816(o[nt], plo[ks], bv[nt >> 1][(nt & 1) * 2], bv[nt >> 1][(nt & 1) * 2 + 1]);
            }
            #pragma unroll
            for (int n4 = 0; n4 < 4; n4++)
                ldsm4(bv[n4], Vl + sw128(((nrow + n4 * 16) << 7) + ks * 32 + bcb));
            #pragma unroll
            for (int nt = 0; nt < 8; nt++)
                mma16816(o[nt], phi[ks], bv[nt >> 1][(nt & 1) * 2], bv[nt >> 1][(nt & 1) * 2 + 1]);
        }
        __syncthreads();
        if (kt + 2 < 16) load_kv(kt + 2, buf);
    }

    l0 += __shfl_xor_sync(0xffffffffu, l0, 1);
    l0 += __shfl_xor_sync(0xffffffffu, l0, 2);
    l1 += __shfl_xor_sync(0xffffffffu, l1, 1);
    l1 += __shfl_xor_sync(0xffffffffu, l1, 2);
    const float i0 = 1.f / l0, i1 = 1.f / l1;
    const int r = lane >> 2, c2 = (lane & 3) << 1;
    const int row0 = b * Ss + q0 + (w << 4) + r;
    __nv_bfloat16* ha = g_A2h + (size_t)row0 * 1024;
    __nv_bfloat16* la = g_A2l + (size_t)row0 * 1024;
    __nv_bfloat16* hb2 = g_A2h + (size_t)(row0 + 8) * 1024;
    __nv_bfloat16* lb2 = g_A2l + (size_t)(row0 + 8) * 1024;
    #pragma unroll
    for (int nt = 0; nt < 8; nt++) {
        const int col = 512 + h * 64 + nt * 8 + c2;
        float r0, r1;
        uint32_t hi = pack_bf2(o[nt][0] * i0, o[nt][1] * i0, r0, r1);
        uint32_t lo = pack_bf2n(r0, r1);
        *(uint32_t*)(ha + col) = hi;
        *(uint32_t*)(la + col) = lo;
        hi = pack_bf2(o[nt][2] * i1, o[nt][3] * i1, r0, r1);
        lo = pack_bf2n(r0, r1);
        *(uint32_t*)(hb2 + col) = hi;
        *(uint32_t*)(lb2 + col) = lo;
    }
}

// ---------------- fp32 SIMT GEMM for Wc: 32x64 tiles, 256 blocks -------------
__global__ void __launch_bounds__(256)
wc_gemm(const float* __restrict__ Wf, const float* __restrict__ Wl_out,
        const float* __restrict__ Wg_out, float* __restrict__ Wc)
{
    __shared__ float As[2][16][33];
    __shared__ float Bs[2][16][68];
    const int g = blockIdx.z;
    const float* A = Wf + (g ? Ee : 0);
    const float* W = g ? Wg_out : Wl_out;
    float* C = Wc + (g ? Ee : 0);
    const int t = threadIdx.x, tx = t & 15, ty = t >> 4;   // ty 0..15 -> 2 rows each
    const int m0 = blockIdx.y * 32, n0 = blockIdx.x * 64;
    const int lr = (t & 127) >> 2, lk = (t & 3) << 2;       // A loaders: t<128
    const int bkk = t >> 4, bcc = (t & 15) << 2;
    float acc[2][4] = {};

    float4 va = make_float4(0.f, 0.f, 0.f, 0.f);
    if (t < 128) va = *(const float4*)(A + (size_t)(m0 + lr) * (2 * Ee) + lk);
    float4 vb = *(const float4*)(W + (size_t)bkk * Ee + n0 + bcc);
    int buf = 0;
    for (int k0 = 0; k0 < Ee; k0 += 16) {
        if (t < 128) {
            As[buf][lk + 0][lr] = va.x; As[buf][lk + 1][lr] = va.y;
            As[buf][lk + 2][lr] = va.z; As[buf][lk + 3][lr] = va.w;
        }
        *(float4*)&Bs[buf][bkk][bcc] = vb;
        __syncthreads();
        if (k0 + 16 < Ee) {
            if (t < 128)
                va = *(const float4*)(A + (size_t)(m0 + lr) * (2 * Ee) + k0 + 16 + lk);
            vb = *(const float4*)(W + (size_t)(k0 + 16 + bkk) * Ee + n0 + bcc);
        }
        #pragma unroll
        for (int kk = 0; kk < 16; kk++) {
            const float a0 = As[buf][kk][ty * 2];
            const float a1 = As[buf][kk][ty * 2 + 1];
            float4 b = *(const float4*)&Bs[buf][kk][tx << 2];
            acc[0][0] = fmaf(a0, b.x, acc[0][0]);
            acc[0][1] = fmaf(a0, b.y, acc[0][1]);
            acc[0][2] = fmaf(a0, b.z, acc[0][2]);
            acc[0][3] = fmaf(a0, b.w, acc[0][3]);
            acc[1][0] = fmaf(a1, b.x, acc[1][0]);
            acc[1][1] = fmaf(a1, b.y, acc[1][1]);
            acc[1][2] = fmaf(a1, b.z, acc[1][2]);
            acc[1][3] = fmaf(a1, b.w, acc[1][3]);
        }
        buf ^= 1;
    }
    #pragma unroll
    for (int i = 0; i < 2; i++)
        *(float4*)(C + (size_t)(m0 + ty * 2 + i) * (2 * Ee) + n0 + (tx << 2)) =
            make_float4(acc[i][0], acc[i][1], acc[i][2], acc[i][3]);
}

// ---------------- combined bias ----------------------------------------------
__global__ void __launch_bounds__(128)
bias_combine_kernel(const float* __restrict__ Wf,
                    const float* __restrict__ bl,
                    const float* __restrict__ bg,
                    const float* __restrict__ bf)
{
    const int o = blockIdx.x;
    const int t = threadIdx.x;
    const float* row = Wf + (size_t)o * (2 * Ee);
    float acc = 0.f;
    for (int j = t; j < Ee; j += 128)
        acc += row[j] * bl[j] + row[Ee + j] * bg[j];
    #pragma unroll
    for (int off = 16; off; off >>= 1)
        acc += __shfl_xor_sync(0xffffffffu, acc, off);
    __shared__ float ws[4];
    if ((t & 31) == 0) ws[t >> 5] = acc;
    __syncthreads();
    if (t == 0) g_bc[o] = ws[0] + ws[1] + ws[2] + ws[3] + bf[o];
}

// ---------------- local (banded) attention -> A2 hi/lo ------------------------
__global__ void __launch_bounds__(256)
local_attn_kernel(const float* __restrict__ qkv)
{
    const int warp = (blockIdx.x * blockDim.x + threadIdx.x) >> 5;
    const int lane = threadIdx.x & 31;
    const int q  = warp & (Ss - 1);
    const int bh = warp >> 10;
    const int b  = bh >> 3, h = bh & 7;

    const float* base = qkv + (size_t)(b * Ss) * QKVN + h * DHd;
    const float* qrow = base + (size_t)q * QKVN;
    const float q0 = qrow[lane], q1 = qrow[lane + 32];

    float s[7];
    float mmax = -1e30f;
    #pragma unroll
    for (int jj = 0; jj < 7; jj++) {
        const int j = q - LOCALW + jj;
        const bool valid = (j >= 0) && (j < Ss);
        float d = 0.f;
        if (valid) {
            const float* krow = base + (size_t)j * QKVN + Ee;
            d = q0 * krow[lane] + q1 * krow[lane + 32];
        }
        #pragma unroll
        for (int off = 16; off; off >>= 1)
            d += __shfl_xor_sync(0xffffffffu, d, off);
        d = valid ? d * 0.125f : -1e30f;
        s[jj] = d;
        mmax = fmaxf(mmax, d);
    }
    float sum = 0.f;
    #pragma unroll
    for (int jj = 0; jj < 7; jj++) { s[jj] = __expf(s[jj] - mmax); sum += s[jj]; }
    const float inv = 1.f / sum;
    float o0 = 0.f, o1 = 0.f;
    #pragma unroll
    for (int jj = 0; jj < 7; jj++) {
        const int j = q - LOCALW + jj;
        if (j >= 0 && j < Ss) {
            const float* vrow = base + (size_t)j * QKVN + 2 * Ee;
            o0 = fmaf(s[jj], vrow[lane],      o0);
            o1 = fmaf(s[jj], vrow[lane + 32], o1);
        }
    }
    const float v0 = o0 * inv, v1 = o1 * inv;
    const float p0 = __shfl_down_sync(0xffffffffu, v0, 1);
    const float p1 = __shfl_down_sync(0xffffffffu, v1, 1);
    if (!(lane & 1)) {
        __nv_bfloat16* a2h = g_A2h + (size_t)(b * Ss + q) * 1024;
        __nv_bfloat16* a2l = g_A2l + (size_t)(b * Ss + q) * 1024;
        const int c0 = h * DHd + lane;
        float r0, r1;
        uint32_t hi = pack_bf2(v0, p0, r0, r1);
        uint32_t lo = pack_bf2n(r0, r1);
        *(uint32_t*)(a2h + c0) = hi;
        *(uint32_t*)(a2l + c0) = lo;
        hi = pack_bf2(v1, p1, r0, r1);
        lo = pack_bf2n(r0, r1);
        *(uint32_t*)(a2h + c0 + 32) = hi;
        *(uint32_t*)(a2l + c0 + 32) = lo;
    }
}

// ---------------- launcher -----------------------------------------------------
extern "C" void kernel_launch(void* const* d_in, const int* in_sizes, int n_in,
                              void* d_out, int out_size)
{
    (void)in_sizes; (void)n_in; (void)out_size;
    const float* x      = (const float*)d_in[0];
    const float* Wl_in  = (const float*)d_in[1];
    const float* bl_in  = (const float*)d_in[2];
    const float* Wl_out = (const float*)d_in[3];
    const float* bl_out = (const float*)d_in[4];
    const float* Wg_in  = (const float*)d_in[5];
    const float* bg_in  = (const float*)d_in[6];
    const float* Wg_out = (const float*)d_in[7];
    const float* bg_out = (const float*)d_in[8];
    const float* Wf     = (const float*)d_in[9];
    const float* bf     = (const float*)d_in[10];
    float* out = (float*)d_out;

    float *qkv_l, *vg, *Wc, *bc;
    __nv_bfloat16 *A1h, *A1l, *A2h, *A2l, *B2h, *B2l, *qkh, *qkl, *vth, *vtl;
    __nv_bfloat16 *B1lh, *B1ll, *B1gh, *B1gl;
    cudaGetSymbolAddress((void**)&qkv_l, g_qkv_l);
    cudaGetSymbolAddress((void**)&vg,    g_vg);
    cudaGetSymbolAddress((void**)&Wc,    g_Wc);
    cudaGetSymbolAddress((void**)&bc,    g_bc);
    cudaGetSymbolAddress((void**)&A1h,   g_A1h);
    cudaGetSymbolAddress((void**)&A1l,   g_A1l);
    cudaGetSymbolAddress((void**)&B1lh,  g_B1lh);
    cudaGetSymbolAddress((void**)&B1ll,  g_B1ll);
    cudaGetSymbolAddress((void**)&B1gh,  g_B1gh);
    cudaGetSymbolAddress((void**)&B1gl,  g_B1gl);
    cudaGetSymbolAddress((void**)&A2h,   g_A2h);
    cudaGetSymbolAddress((void**)&A2l,   g_A2l);
    cudaGetSymbolAddress((void**)&B2h,   g_B2h);
    cudaGetSymbolAddress((void**)&B2l,   g_B2l);
    cudaGetSymbolAddress((void**)&qkh,   g_qk_h);
    cudaGetSymbolAddress((void**)&qkl,   g_qk_l);
    cudaGetSymbolAddress((void**)&vth,   g_vt_h);
    cudaGetSymbolAddress((void**)&vtl,   g_vt_l);

    cudaFuncSetAttribute(mma_gemm3,
                         cudaFuncAttributeMaxDynamicSharedMemorySize, MMA_SMEM3);
    cudaFuncSetAttribute(qkv_fused,
                         cudaFuncAttributeMaxDynamicSharedMemorySize, MMA_SMEM3);
    cudaFuncSetAttribute(flash_attn,
                         cudaFuncAttributeMaxDynamicSharedMemorySize, AT_SMEM);

    // 1) hi/lo splits of x and input-proj weights (round-11 structure)
    split2<<<(Mm * Ee) / 1024, 256>>>(x, A1h, A1l);
    split2<<<(QKVN * Ee) / 1024, 256>>>(Wl_in, B1lh, B1ll);
    split2<<<(QKVN * Ee) / 1024, 256>>>(Wg_in, B1gh, B1gl);

    // 2) combined epilogue weights (32x64 tiles, 256 blocks) + bias + split
    wc_gemm<<<dim3(8, 16, 2), 256>>>(Wf, Wl_out, Wg_out, Wc);
    bias_combine_kernel<<<Ee, 128>>>(Wf, bl_out, bg_out, bf);
    split2<<<(Ee * 2 * Ee) / 1024, 256>>>(Wc, B2h, B2l);

    // 3) fused QKV projections (round-11 proven 3-stage core, 3 CTA/SM)
    qkv_fused<<<dim3(QKVN / 64, Mm / 128, 2), 128, MMA_SMEM3>>>(
        A1h, A1l, bl_in, bg_in);

    // 4) local attention -> A2
    local_attn_kernel<<<(Bb * Hh * Ss) / 8, 256>>>(qkv_l);

    // 5) V transpose-split, flash attention
    vt_split<<<dim3(Ss / 64, Bb * Hh), 256>>>(vg, vth, vtl);
    flash_attn<<<dim3(Ss / 64, Bb * Hh), 128, AT_SMEM>>>(qkh, qkl, vth, vtl);

    // 6) final fused projection + ReLU
    mma_gemm3<<<dim3(Ee / 64, Mm / 128), 128, MMA_SMEM3>>>(
        A2h, A2l, B2h, B2l, bc, out, 1024, Ee);
}

// round 17
// speedup vs baseline: 1.1469x; 1.0172x over previous
#include <cuda_runtime.h>
#include <cuda_bf16.h>
#include <math.h>
#include <stdint.h>

// Problem constants
#define Bb   8
#define Ss   1024
#define Ee   512
#define Hh   8
#define DHd  64
#define Mm   (Bb * Ss)        // 8192
#define QKVN (3 * Ee)         // 1536
#define LOCALW 3

// ---------------- scratch (device globals) ----------------------------------
__device__ float g_qkv_l[(size_t)Mm * QKVN];
__device__ float g_vg   [(size_t)Mm * Ee];
__device__ float g_Wc   [(size_t)Ee * 2 * Ee];
__device__ float g_bc   [Ee];
__device__ __nv_bfloat16 g_A1h[(size_t)Mm * Ee];
__device__ __nv_bfloat16 g_A1l[(size_t)Mm * Ee];
__device__ __nv_bfloat16 g_B1lh[(size_t)QKVN * Ee];
__device__ __nv_bfloat16 g_B1ll[(size_t)QKVN * Ee];
__device__ __nv_bfloat16 g_B1gh[(size_t)QKVN * Ee];
__device__ __nv_bfloat16 g_B1gl[(size_t)QKVN * Ee];
__device__ __nv_bfloat16 g_A2h[(size_t)Mm * 1024];
__device__ __nv_bfloat16 g_A2l[(size_t)Mm * 1024];
__device__ __nv_bfloat16 g_B2h[(size_t)Ee * 1024];
__device__ __nv_bfloat16 g_B2l[(size_t)Ee * 1024];
__device__ __nv_bfloat16 g_qk_h[(size_t)Mm * 1024];
__device__ __nv_bfloat16 g_qk_l[(size_t)Mm * 1024];
__device__ __nv_bfloat16 g_vt_h[(size_t)64 * 64 * Ss];
__device__ __nv_bfloat16 g_vt_l[(size_t)64 * 64 * Ss];

// ---------------- PTX helpers (base ISA only) --------------------------------
__device__ __forceinline__ uint32_t smem_u32(const void* p) {
    uint32_t a;
    asm("{ .reg .u64 t; cvta.to.shared.u64 t, %1; cvt.u32.u64 %0, t; }"
        : "=r"(a) : "l"(p));
    return a;
}
__device__ __forceinline__ uint32_t sw128(uint32_t o) { return o ^ ((o >> 3) & 0x70); }
__device__ __forceinline__ uint32_t sw64(uint32_t o)  { return o ^ ((o >> 3) & 0x30); }

__device__ __forceinline__ void cp16(uint32_t dst, const void* src) {
    asm volatile("cp.async.cg.shared.global [%0], [%1], 16;"
                 :: "r"(dst), "l"(src) : "memory");
}
__device__ __forceinline__ void ldsm4(uint32_t* d, uint32_t a) {
    asm volatile("ldmatrix.sync.aligned.m8n8.x4.shared.b16 {%0,%1,%2,%3}, [%4];"
                 : "=r"(d[0]), "=r"(d[1]), "=r"(d[2]), "=r"(d[3]) : "r"(a));
}
__device__ __forceinline__ void mma16816(float* c, const uint32_t* a,
                                         uint32_t b0, uint32_t b1) {
    asm volatile("mma.sync.aligned.m16n8k16.row.col.f32.bf16.bf16.f32 "
                 "{%0,%1,%2,%3}, {%4,%5,%6,%7}, {%8,%9}, {%0,%1,%2,%3};"
                 : "+f"(c[0]), "+f"(c[1]), "+f"(c[2]), "+f"(c[3])
                 : "r"(a[0]), "r"(a[1]), "r"(a[2]), "r"(a[3]), "r"(b0), "r"(b1));
}
__device__ __forceinline__ uint32_t pack_bf2(float a, float b, float& ra, float& rb) {
    __nv_bfloat16 ha = __float2bfloat16(a), hb = __float2bfloat16(b);
    ra = a - __bfloat162float(ha);
    rb = b - __bfloat162float(hb);
    return ((uint32_t)*(uint16_t*)&hb << 16) | (uint32_t)*(uint16_t*)&ha;
}
__device__ __forceinline__ uint32_t pack_bf2n(float a, float b) {
    __nv_bfloat16 ha = __float2bfloat16(a), hb = __float2bfloat16(b);
    return ((uint32_t)*(uint16_t*)&hb << 16) | (uint32_t)*(uint16_t*)&ha;
}

// ======== 3-term hi/lo GEMM core: 128 thr, tile 128Mx64N, K-chunk 32 =========
// Round-11 proven core: 3 stages x 24KB = 72KB -> 3 CTA/SM.
#define MMA_SMEM3 73728

#define GEMM_CORE3()                                                            \
    auto load_stage = [&](int c, int sbuf) {                                    \
        const uint32_t st = sbase + sbuf * 24576;                               \
        const size_t cb = (size_t)c * 64;                                       \
        _Pragma("unroll")                                                       \
        for (int i = 0; i < 4; i++) {                                           \
            const int idx = t + (i << 7);                                       \
            const int row = idx >> 2;                                           \
            const int sc  = (idx & 3) << 4;                                     \
            const uint32_t off = sw64((row << 6) + sc);                         \
            const size_t go = (size_t)row * krow + cb + sc;                     \
            cp16(st + off,        Aph + go);                                    \
            cp16(st + 8192 + off, Apl + go);                                    \
        }                                                                       \
        _Pragma("unroll")                                                       \
        for (int i = 0; i < 2; i++) {                                           \
            const int idx = t + (i << 7);                                       \
            const int row = idx >> 2;                                           \
            const int sc  = (idx & 3) << 4;                                     \
            const uint32_t off = sw64((row << 6) + sc);                         \
            const size_t go = (size_t)row * krow + cb + sc;                     \
            cp16(st + 16384 + off, Bph + go);                                   \
            cp16(st + 20480 + off, Bpl + go);                                   \
        }                                                                       \
        asm volatile("cp.async.commit_group;" ::: "memory");                    \
    };                                                                          \
    load_stage(0, 0); load_stage(1, 1); load_stage(2, 2);                       \
    float acc[2][8][4] = {};                                                    \
    const int arow0 = w * 32 + (lane & 15);                                     \
    const int acb   = (lane >> 4) << 4;                                         \
    const int nrow0 = ((lane >> 4) & 1) * 8 + (lane & 7);                       \
    const int bcb   = ((lane >> 3) & 1) << 4;                                   \
    int buf = 0;                                                                \
    for (int c = 0; c < KC; c++) {                                              \
        if (c + 2 < KC)      asm volatile("cp.async.wait_group 2;" ::: "memory"); \
        else if (c + 1 < KC) asm volatile("cp.async.wait_group 1;" ::: "memory"); \
        else                 asm volatile("cp.async.wait_group 0;" ::: "memory"); \
        __syncthreads();                                                        \
        const uint32_t sAh = sbase + buf * 24576;                               \
        const uint32_t sAl = sAh + 8192;                                        \
        const uint32_t sBh = sAh + 16384;                                       \
        const uint32_t sBl = sAh + 20480;                                       \
        _Pragma("unroll")                                                       \
        for (int ks = 0; ks < 2; ks++) {                                        \
            uint32_t ah[2][4], al[2][4];                                        \
            _Pragma("unroll")                                                   \
            for (int mt = 0; mt < 2; mt++) {                                    \
                const uint32_t ro = sw64(((arow0 + mt * 16) << 6) + ks * 32 + acb); \
                ldsm4(ah[mt], sAh + ro);                                        \
                ldsm4(al[mt], sAl + ro);                                        \
            }                                                                   \
            uint32_t bh[4][4], bl_[4][4];                                       \
            _Pragma("unroll")                                                   \
            for (int n4 = 0; n4 < 4; n4++) {                                    \
                const uint32_t ro = sw64(((nrow0 + n4 * 16) << 6) + ks * 32 + bcb); \
                ldsm4(bh[n4], sBh + ro);                                        \
                ldsm4(bl_[n4], sBl + ro);                                       \
            }                                                                   \
            _Pragma("unroll")                                                   \
            for (int mt = 0; mt < 2; mt++)                                      \
                _Pragma("unroll")                                               \
                for (int nt = 0; nt < 8; nt++) {                                \
                    const uint32_t h0 = bh[nt >> 1][(nt & 1) * 2];              \
                    const uint32_t h1 = bh[nt >> 1][(nt & 1) * 2 + 1];          \
                    mma16816(acc[mt][nt], ah[mt], h0, h1);                      \
                    mma16816(acc[mt][nt], al[mt], h0, h1);                      \
                    mma16816(acc[mt][nt], ah[mt],                               \
                             bl_[nt >> 1][(nt & 1) * 2], bl_[nt >> 1][(nt & 1) * 2 + 1]); \
                }                                                               \
        }                                                                       \
        __syncthreads();                                                        \
        if (c + 3 < KC) load_stage(c + 3, buf);                                 \
        buf = (buf == 2) ? 0 : buf + 1;                                         \
    }

// ---------------- final GEMM: out = relu(A2 @ B2^T + bc) --------------------
__global__ void __launch_bounds__(128)
mma_gemm3(const __nv_bfloat16* __restrict__ Ah, const __nv_bfloat16* __restrict__ Al,
          const __nv_bfloat16* __restrict__ Bh, const __nv_bfloat16* __restrict__ Bl,
          const float* __restrict__ bias, float* __restrict__ C, int K, int ldc)
{
    extern __shared__ char sm[];
    const uint32_t sbase = smem_u32(sm);
    const int t = threadIdx.x, lane = t & 31, w = t >> 5;
    const int m0 = blockIdx.y << 7, n0 = blockIdx.x << 6;
    const char* Aph = (const char*)(Ah + (size_t)m0 * K);
    const char* Apl = (const char*)(Al + (size_t)m0 * K);
    const char* Bph = (const char*)(Bh + (size_t)n0 * K);
    const char* Bpl = (const char*)(Bl + (size_t)n0 * K);
    const size_t krow = (size_t)K * 2;
    const int KC = K >> 5;

    GEMM_CORE3()

    const int erow = m0 + w * 32 + (lane >> 2);
    const int ecol = n0 + ((lane & 3) << 1);
    #pragma unroll
    for (int nt = 0; nt < 8; nt++) {
        const int gn = ecol + nt * 8;
        const float2 bb2 = *(const float2*)(bias + gn);
        #pragma unroll
        for (int mt = 0; mt < 2; mt++) {
            #pragma unroll
            for (int half = 0; half < 2; half++) {
                float v0 = fmaxf(acc[mt][nt][half * 2 + 0] + bb2.x, 0.f);
                float v1 = fmaxf(acc[mt][nt][half * 2 + 1] + bb2.y, 0.f);
                const int gm = erow + mt * 16 + half * 8;
                *(float2*)(C + (size_t)gm * ldc + gn) = make_float2(v0, v1);
            }
        }
    }
}

// ---------------- fused QKV GEMM (both blocks via blockIdx.z) ----------------
__global__ void __launch_bounds__(128)
qkv_fused(const __nv_bfloat16* __restrict__ Ah, const __nv_bfloat16* __restrict__ Al,
          const float* __restrict__ bl, const float* __restrict__ bg)
{
    extern __shared__ char sm[];
    const uint32_t sbase = smem_u32(sm);
    const int t = threadIdx.x, lane = t & 31, w = t >> 5;
    const int m0 = blockIdx.y << 7, n0 = blockIdx.x << 6;
    const int z = blockIdx.z;
    const int K = Ee;
    const float* bias = z ? bg : bl;
    const char* Aph = (const char*)(Ah + (size_t)m0 * K);
    const char* Apl = (const char*)(Al + (size_t)m0 * K);
    const char* Bph = (const char*)((z ? g_B1gh : g_B1lh) + (size_t)n0 * K);
    const char* Bpl = (const char*)((z ? g_B1gl : g_B1ll) + (size_t)n0 * K);
    const size_t krow = (size_t)K * 2;
    const int KC = K >> 5;

    GEMM_CORE3()

    const int erow = m0 + w * 32 + (lane >> 2);
    const int ecol = n0 + ((lane & 3) << 1);
    #pragma unroll
    for (int nt = 0; nt < 8; nt++) {
        const int gn = ecol + nt * 8;
        const float2 bb2 = *(const float2*)(bias + gn);
        #pragma unroll
        for (int mt = 0; mt < 2; mt++) {
            #pragma unroll
            for (int half = 0; half < 2; half++) {
                const float v0 = acc[mt][nt][half * 2 + 0] + bb2.x;
                const float v1 = acc[mt][nt][half * 2 + 1] + bb2.y;
                const int gm = erow + mt * 16 + half * 8;
                if (z == 0) {
                    *(float2*)(g_qkv_l + (size_t)gm * QKVN + gn) = make_float2(v0, v1);
                } else if (n0 < 1024) {
                    float r0, r1;
                    const uint32_t hi = pack_bf2(v0, v1, r0, r1);
                    const uint32_t lo = pack_bf2n(r0, r1);
                    *(uint32_t*)(g_qk_h + (size_t)gm * 1024 + gn) = hi;
                    *(uint32_t*)(g_qk_l + (size_t)gm * 1024 + gn) = lo;
                } else {
                    *(float2*)(g_vg + (size_t)gm * Ee + (gn - 1024)) = make_float2(v0, v1);
                }
            }
        }
    }
}

// ---------------- elementwise hi/lo split ------------------------------------
__global__ void split2(const float* __restrict__ in,
                       __nv_bfloat16* __restrict__ oh, __nv_bfloat16* __restrict__ ol)
{
    const size_t i = ((size_t)blockIdx.x * 256 + threadIdx.x) << 2;
    const float4 v = *(const float4*)(in + i);
    float vv[4] = {v.x, v.y, v.z, v.w};
    union { __nv_bfloat16 b[4]; uint2 u; } hu, lu;
    #pragma unroll
    for (int j = 0; j < 4; j++) {
        hu.b[j] = __float2bfloat16(vv[j]);
        lu.b[j] = __float2bfloat16(vv[j] - __bfloat162float(hu.b[j]));
    }
    *(uint2*)(oh + i) = hu.u;
    *(uint2*)(ol + i) = lu.u;
}

// transpose + split V
__global__ void __launch_bounds__(256)
vt_split(const float* __restrict__ vg,
         __nv_bfloat16* __restrict__ vh, __nv_bfloat16* __restrict__ vl)
{
    __shared__ float tile[64][65];
    const int t = threadIdx.x;
    const int bh = blockIdx.y, b = bh >> 3, h = bh & 7;
    const int s0 = blockIdx.x << 6;
    #pragma unroll
    for (int i = 0; i < 4; i++) {
        const int idx = t + (i << 8);
        const int row = idx >> 4, c4 = (idx & 15) << 2;
        float4 v = *(const float4*)(vg + (size_t)(b * Ss + s0 + row) * Ee + h * 64 + c4);
        tile[row][c4] = v.x; tile[row][c4 + 1] = v.y;
        tile[row][c4 + 2] = v.z; tile[row][c4 + 3] = v.w;
    }
    __syncthreads();
    #pragma unroll
    for (int i = 0; i < 4; i++) {
        const int idx = t + (i << 8);
        const int d = idx >> 4, sc = (idx & 15) << 2;
        uint16_t hh[4], ll[4];
        #pragma unroll
        for (int k = 0; k < 4; k++) {
            const float f = tile[sc + k][d];
            __nv_bfloat16 hb = __float2bfloat16(f);
            const float lf = f - __bfloat162float(hb);
            __nv_bfloat16 lb = __float2bfloat16(lf);
            hh[k] = *(uint16_t*)&hb; ll[k] = *(uint16_t*)&lb;
        }
        uint2 hv = make_uint2((uint32_t)hh[0] | ((uint32_t)hh[1] << 16),
                              (uint32_t)hh[2] | ((uint32_t)hh[3] << 16));
        uint2 lv = make_uint2((uint32_t)ll[0] | ((uint32_t)ll[1] << 16),
                              (uint32_t)ll[2] | ((uint32_t)ll[3] << 16));
        *(uint2*)(vh + (size_t)(bh * 64 + d) * Ss + s0 + sc) = hv;
        *(uint2*)(vl + (size_t)(bh * 64 + d) * Ss + s0 + sc) = lv;
    }
}

// ---------------- flash attention: 128 threads, 64-query tiles ---------------
#define AT_SMEM 81920

#define S_TERM(AF, KB)                                                          \
    _Pragma("unroll")                                                           \
    for (int ks = 0; ks < 4; ks++) {                                            \
        uint32_t bfr[4][4];                                                     \
        _Pragma("unroll")                                                       \
        for (int n4 = 0; n4 < 4; n4++)                                          \
            ldsm4(bfr[n4], (KB) + sw128(((nrow + n4 * 16) << 7) + ks * 32 + bcb)); \
        _Pragma("unroll")                                                       \
        for (int nt = 0; nt < 8; nt++)                                          \
            mma16816(sA[nt], AF[ks],                                            \
                     bfr[nt >> 1][(nt & 1) * 2], bfr[nt >> 1][(nt & 1) * 2 + 1]); \
    }

__global__ void __launch_bounds__(128)
flash_attn(const __nv_bfloat16* __restrict__ qkh, const __nv_bfloat16* __restrict__ qkl,
           const __nv_bfloat16* __restrict__ vth, const __nv_bfloat16* __restrict__ vtl)
{
    extern __shared__ char sm[];
    const uint32_t sb = smem_u32(sm);
    const int t = threadIdx.x, lane = t & 31, w = t >> 5;
    const int bh = blockIdx.y, b = bh >> 3, h = bh & 7;
    const int q0 = blockIdx.x << 6;
    const uint32_t Qh = sb, Ql = sb + 8192;

    {
        const char* srch = (const char*)(qkh + (size_t)(b * Ss + q0) * 1024 + h * 64);
        const char* srcl = (const char*)(qkl + (size_t)(b * Ss + q0) * 1024 + h * 64);
        #pragma unroll
        for (int i = 0; i < 4; i++) {
            const int idx = t + (i << 7);
            const int row = idx >> 3, ch = (idx & 7) << 4;
            const uint32_t off = sw128((row << 7) | ch);
            cp16(Qh + off, srch + (size_t)row * 2048 + ch);
            cp16(Ql + off, srcl + (size_t)row * 2048 + ch);
        }
        asm volatile("cp.async.commit_group;" ::: "memory");
    }

    auto load_kv = [&](int kt, int buf) {
        const uint32_t bb = sb + 16384 + buf * 32768;
        const char* kh = (const char*)(qkh + (size_t)(b * Ss + kt * 64) * 1024 + 512 + h * 64);
        const char* kl = (const char*)(qkl + (size_t)(b * Ss + kt * 64) * 1024 + 512 + h * 64);
        const char* vh = (const char*)(vth + (size_t)(bh * 64) * Ss + kt * 64);
        const char* vl = (const char*)(vtl + (size_t)(bh * 64) * Ss + kt * 64);
        #pragma unroll
        for (int i = 0; i < 4; i++) {
            const int idx = t + (i << 7);
            const int row = idx >> 3, ch = (idx & 7) << 4;
            const uint32_t off = sw128((row << 7) | ch);
            cp16(bb + off,         kh + (size_t)row * 2048 + ch);
            cp16(bb + 8192 + off,  kl + (size_t)row * 2048 + ch);
            cp16(bb + 16384 + off, vh + (size_t)row * 2048 + ch);
            cp16(bb + 24576 + off, vl + (size_t)row * 2048 + ch);
        }
        asm volatile("cp.async.commit_group;" ::: "memory");
    };
    load_kv(0, 0);
    load_kv(1, 1);

    asm volatile("cp.async.wait_group 2;" ::: "memory");
    __syncthreads();

    const int arow = (w << 4) + (lane & 15);
    const int acb  = (lane >> 4) << 4;
    uint32_t qh[4][4], ql[4][4];
    #pragma unroll
    for (int ks = 0; ks < 4; ks++) {
        ldsm4(qh[ks], Qh + sw128((arow << 7) + ks * 32 + acb));
        ldsm4(ql[ks], Ql + sw128((arow << 7) + ks * 32 + acb));
    }

    const int nrow = ((lane >> 4) & 1) * 8 + (lane & 7);
    const int bcb  = ((lane >> 3) & 1) << 4;

    float o[8][4] = {};
    float m0 = -INFINITY, m1 = -INFINITY, l0 = 0.f, l1 = 0.f;

    for (int kt = 0; kt < 16; kt++) {
        const int buf = kt & 1;
        if (kt + 1 < 16) asm volatile("cp.async.wait_group 1;" ::: "memory");
        else             asm volatile("cp.async.wait_group 0;" ::: "memory");
        __syncthreads();
        const uint32_t Kh = sb + 16384 + buf * 32768;
        const uint32_t Kl = Kh + 8192, Vh = Kh + 16384, Vl = Kh + 24576;

        float sA[8][4] = {};
        S_TERM(qh, Kh)
        S_TERM(qh, Kl)
        S_TERM(ql, Kh)

        float rm0 = -INFINITY, rm1 = -INFINITY;
        #pragma unroll
        for (int nt = 0; nt < 8; nt++) {
            #pragma unroll
            for (int j = 0; j < 4; j++) sA[nt][j] *= 0.125f;
            rm0 = fmaxf(rm0, fmaxf(sA[nt][0], sA[nt][1]));
            rm1 = fmaxf(rm1, fmaxf(sA[nt][2], sA[nt][3]));
        }
        rm0 = fmaxf(rm0, __shfl_xor_sync(0xffffffffu, rm0, 1));
        rm0 = fmaxf(rm0, __shfl_xor_sync(0xffffffffu, rm0, 2));
        rm1 = fmaxf(rm1, __shfl_xor_sync(0xffffffffu, rm1, 1));
        rm1 = fmaxf(rm1, __shfl_xor_sync(0xffffffffu, rm1, 2));
        const float mn0 = fmaxf(m0, rm0), mn1 = fmaxf(m1, rm1);
        const float sc0 = __expf(m0 - mn0), sc1 = __expf(m1 - mn1);
        m0 = mn0; m1 = mn1;

        float ps0 = 0.f, ps1 = 0.f;
        uint32_t phi[4][4], plo[4][4];
        #pragma unroll
        for (int j = 0; j < 4; j++) {
            float p[2][4];
            #pragma unroll
            for (int e = 0; e < 2; e++) {
                p[e][0] = __expf(sA[2 * j + e][0] - mn0);
                p[e][1] = __expf(sA[2 * j + e][1] - mn0);
                p[e][2] = __expf(sA[2 * j + e][2] - mn1);
                p[e][3] = __expf(sA[2 * j + e][3] - mn1);
                ps0 += p[e][0] + p[e][1];
                ps1 += p[e][2] + p[e][3];
            }
            float r0, r1;
            phi[j][0] = pack_bf2(p[0][0], p[0][1], r0, r1); plo[j][0] = pack_bf2n(r0, r1);
            phi[j][1] = pack_bf2(p[0][2], p[0][3], r0, r1); plo[j][1] = pack_bf2n(r0, r1);
            phi[j][2] = pack_bf2(p[1][0], p[1][1], r0, r1); plo[j][2] = pack_bf2n(r0, r1);
            phi[j][3] = pack_bf2(p[1][2], p[1][3], r0, r1); plo[j][3] = pack_bf2n(r0, r1);
        }
        l0 = l0 * sc0 + ps0;
        l1 = l1 * sc1 + ps1;
        #pragma unroll
        for (int nt = 0; nt < 8; nt++) {
            o[nt][0] *= sc0; o[nt][1] *= sc0;
            o[nt][2] *= sc1; o[nt][3] *= sc1;
        }

        #pragma unroll
        for (int ks = 0; ks < 4; ks++) {
            uint32_t bv[4][4];
            #pragma unroll
            for (int n4 = 0; n4 < 4; n4++)
                ldsm4(bv[n4], Vh + sw128(((nrow + n4 * 16) << 7) + ks * 32 + bcb));
            #pragma unroll
            for (int nt = 0; nt < 8; nt++) {
                mma16816(o[nt], phi[ks], bv[nt >> 1][(nt & 1) * 2], bv[nt >> 1][(nt & 1) * 2 + 1]);
                mma16816(o[nt], plo[ks], bv[nt >> 1][(nt & 1) * 2], bv[nt >> 1][(nt & 1) * 2 + 1]);
            }
            #pragma unroll
            for (int n4 = 0; n4 < 4; n4++)
                ldsm4(bv[n4], Vl + sw128(((nrow + n4 * 16) << 7) + ks * 32 + bcb));
            #pragma unroll
            for (int nt = 0; nt < 8; nt++)
                mma16816(o[nt], phi[ks], bv[nt >> 1][(nt & 1) * 2], bv[nt >> 1][(nt & 1) * 2 + 1]);
        }
        __syncthreads();
        if (kt + 2 < 16) load_kv(kt + 2, buf);
    }

    l0 += __shfl_xor_sync(0xffffffffu, l0, 1);
    l0 += __shfl_xor_sync(0xffffffffu, l0, 2);
    l1 += __shfl_xor_sync(0xffffffffu, l1, 1);
    l1 += __shfl_xor_sync(0xffffffffu, l1, 2);
    const float i0 = 1.f / l0, i1 = 1.f / l1;
    const int r = lane >> 2, c2 = (lane & 3) << 1;
    const int row0 = b * Ss + q0 + (w << 4) + r;
    __nv_bfloat16* ha = g_A2h + (size_t)row0 * 1024;
    __nv_bfloat16* la = g_A2l + (size_t)row0 * 1024;
    __nv_bfloat16* hb2 = g_A2h + (size_t)(row0 + 8) * 1024;
    __nv_bfloat16* lb2 = g_A2l + (size_t)(row0 + 8) * 1024;
    #pragma unroll
    for (int nt = 0; nt < 8; nt++) {
        const int col = 512 + h * 64 + nt * 8 + c2;
        float r0, r1;
        uint32_t hi = pack_bf2(o[nt][0] * i0, o[nt][1] * i0, r0, r1);
        uint32_t lo = pack_bf2n(r0, r1);
        *(uint32_t*)(ha + col) = hi;
        *(uint32_t*)(la + col) = lo;
        hi = pack_bf2(o[nt][2] * i1, o[nt][3] * i1, r0, r1);
        lo = pack_bf2n(r0, r1);
        *(uint32_t*)(hb2 + col) = hi;
        *(uint32_t*)(lb2 + col) = lo;
    }
}

// ---------------- fp32 SIMT GEMM for Wc (round-11 64x64 double-buffered) -----
__global__ void __launch_bounds__(256)
wc_gemm(const float* __restrict__ Wf, const float* __restrict__ Wl_out,
        const float* __restrict__ Wg_out, float* __restrict__ Wc)
{
    __shared__ float As[2][16][68];
    __shared__ float Bs[2][16][68];
    const int g = blockIdx.z;
    const float* A = Wf + (g ? Ee : 0);
    const float* W = g ? Wg_out : Wl_out;
    float* C = Wc + (g ? Ee : 0);
    const int t = threadIdx.x, tx = t & 15, ty = t >> 4;
    const int m0 = blockIdx.y * 64, n0 = blockIdx.x * 64;
    const int lr = t >> 2, lk = (t & 3) << 2;
    const int bkk = t >> 4, bcc = (t & 15) << 2;
    float acc[4][4] = {};

    float4 va = *(const float4*)(A + (size_t)(m0 + lr) * (2 * Ee) + lk);
    float4 vb = *(const float4*)(W + (size_t)bkk * Ee + n0 + bcc);
    int buf = 0;
    for (int k0 = 0; k0 < Ee; k0 += 16) {
        As[buf][lk + 0][lr] = va.x; As[buf][lk + 1][lr] = va.y;
        As[buf][lk + 2][lr] = va.z; As[buf][lk + 3][lr] = va.w;
        *(float4*)&Bs[buf][bkk][bcc] = vb;
        __syncthreads();
        if (k0 + 16 < Ee) {
            va = *(const float4*)(A + (size_t)(m0 + lr) * (2 * Ee) + k0 + 16 + lk);
            vb = *(const float4*)(W + (size_t)(k0 + 16 + bkk) * Ee + n0 + bcc);
        }
        #pragma unroll
        for (int kk = 0; kk < 16; kk++) {
            float4 a = *(const float4*)&As[buf][kk][ty << 2];
            float4 b = *(const float4*)&Bs[buf][kk][tx << 2];
            float av[4] = {a.x, a.y, a.z, a.w};
            float bv[4] = {b.x, b.y, b.z, b.w};
            #pragma unroll
            for (int i = 0; i < 4; i++)
                #pragma unroll
                for (int j = 0; j < 4; j++)
                    acc[i][j] = fmaf(av[i], bv[j], acc[i][j]);
        }
        buf ^= 1;
    }
    #pragma unroll
    for (int i = 0; i < 4; i++)
        *(float4*)(C + (size_t)(m0 + (ty << 2) + i) * (2 * Ee) + n0 + (tx << 2)) =
            make_float4(acc[i][0], acc[i][1], acc[i][2], acc[i][3]);
}

// ---------------- combined bias ----------------------------------------------
__global__ void __launch_bounds__(128)
bias_combine_kernel(const float* __restrict__ Wf,
                    const float* __restrict__ bl,
                    const float* __restrict__ bg,
                    const float* __restrict__ bf)
{
    const int o = blockIdx.x;
    const int t = threadIdx.x;
    const float* row = Wf + (size_t)o * (2 * Ee);
    float acc = 0.f;
    for (int j = t; j < Ee; j += 128)
        acc += row[j] * bl[j] + row[Ee + j] * bg[j];
    #pragma unroll
    for (int off = 16; off; off >>= 1)
        acc += __shfl_xor_sync(0xffffffffu, acc, off);
    __shared__ float ws[4];
    if ((t & 31) == 0) ws[t >> 5] = acc;
    __syncthreads();
    if (t == 0) g_bc[o] = ws[0] + ws[1] + ws[2] + ws[3] + bf[o];
}

// ---------------- local (banded) attention -> A2 hi/lo ------------------------
__global__ void __launch_bounds__(256)
local_attn_kernel(const float* __restrict__ qkv)
{
    const int warp = (blockIdx.x * blockDim.x + threadIdx.x) >> 5;
    const int lane = threadIdx.x & 31;
    const int q  = warp & (Ss - 1);
    const int bh = warp >> 10;
    const int b  = bh >> 3, h = bh & 7;

    const float* base = qkv + (size_t)(b * Ss) * QKVN + h * DHd;
    const float* qrow = base + (size_t)q * QKVN;
    const float q0 = qrow[lane], q1 = qrow[lane + 32];

    float s[7];
    float mmax = -1e30f;
    #pragma unroll
    for (int jj = 0; jj < 7; jj++) {
        const int j = q - LOCALW + jj;
        const bool valid = (j >= 0) && (j < Ss);
        float d = 0.f;
        if (valid) {
            const float* krow = base + (size_t)j * QKVN + Ee;
            d = q0 * krow[lane] + q1 * krow[lane + 32];
        }
        #pragma unroll
        for (int off = 16; off; off >>= 1)
            d += __shfl_xor_sync(0xffffffffu, d, off);
        d = valid ? d * 0.125f : -1e30f;
        s[jj] = d;
        mmax = fmaxf(mmax, d);
    }
    float sum = 0.f;
    #pragma unroll
    for (int jj = 0; jj < 7; jj++) { s[jj] = __expf(s[jj] - mmax); sum += s[jj]; }
    const float inv = 1.f / sum;
    float o0 = 0.f, o1 = 0.f;
    #pragma unroll
    for (int jj = 0; jj < 7; jj++) {
        const int j = q - LOCALW + jj;
        if (j >= 0 && j < Ss) {
            const float* vrow = base + (size_t)j * QKVN + 2 * Ee;
            o0 = fmaf(s[jj], vrow[lane],      o0);
            o1 = fmaf(s[jj], vrow[lane + 32], o1);
        }
    }
    const float v0 = o0 * inv, v1 = o1 * inv;
    const float p0 = __shfl_down_sync(0xffffffffu, v0, 1);
    const float p1 = __shfl_down_sync(0xffffffffu, v1, 1);
    if (!(lane & 1)) {
        __nv_bfloat16* a2h = g_A2h + (size_t)(b * Ss + q) * 1024;
        __nv_bfloat16* a2l = g_A2l + (size_t)(b * Ss + q) * 1024;
        const int c0 = h * DHd + lane;
        float r0, r1;
        uint32_t hi = pack_bf2(v0, p0, r0, r1);
        uint32_t lo = pack_bf2n(r0, r1);
        *(uint32_t*)(a2h + c0) = hi;
        *(uint32_t*)(a2l + c0) = lo;
        hi = pack_bf2(v1, p1, r0, r1);
        lo = pack_bf2n(r0, r1);
        *(uint32_t*)(a2h + c0 + 32) = hi;
        *(uint32_t*)(a2l + c0 + 32) = lo;
    }
}

// ---------------- launcher -----------------------------------------------------
extern "C" void kernel_launch(void* const* d_in, const int* in_sizes, int n_in,
                              void* d_out, int out_size)
{
    (void)in_sizes; (void)n_in; (void)out_size;
    const float* x      = (const float*)d_in[0];
    const float* Wl_in  = (const float*)d_in[1];
    const float* bl_in  = (const float*)d_in[2];
    const float* Wl_out = (const float*)d_in[3];
    const float* bl_out = (const float*)d_in[4];
    const float* Wg_in  = (const float*)d_in[5];
    const float* bg_in  = (const float*)d_in[6];
    const float* Wg_out = (const float*)d_in[7];
    const float* bg_out = (const float*)d_in[8];
    const float* Wf     = (const float*)d_in[9];
    const float* bf     = (const float*)d_in[10];
    float* out = (float*)d_out;

    float *qkv_l, *vg, *Wc, *bc;
    __nv_bfloat16 *A1h, *A1l, *A2h, *A2l, *B2h, *B2l, *qkh, *qkl, *vth, *vtl;
    __nv_bfloat16 *B1lh, *B1ll, *B1gh, *B1gl;
    cudaGetSymbolAddress((void**)&qkv_l, g_qkv_l);
    cudaGetSymbolAddress((void**)&vg,    g_vg);
    cudaGetSymbolAddress((void**)&Wc,    g_Wc);
    cudaGetSymbolAddress((void**)&bc,    g_bc);
    cudaGetSymbolAddress((void**)&A1h,   g_A1h);
    cudaGetSymbolAddress((void**)&A1l,   g_A1l);
    cudaGetSymbolAddress((void**)&B1lh,  g_B1lh);
    cudaGetSymbolAddress((void**)&B1ll,  g_B1ll);
    cudaGetSymbolAddress((void**)&B1gh,  g_B1gh);
    cudaGetSymbolAddress((void**)&B1gl,  g_B1gl);
    cudaGetSymbolAddress((void**)&A2h,   g_A2h);
    cudaGetSymbolAddress((void**)&A2l,   g_A2l);
    cudaGetSymbolAddress((void**)&B2h,   g_B2h);
    cudaGetSymbolAddress((void**)&B2l,   g_B2l);
    cudaGetSymbolAddress((void**)&qkh,   g_qk_h);
    cudaGetSymbolAddress((void**)&qkl,   g_qk_l);
    cudaGetSymbolAddress((void**)&vth,   g_vt_h);
    cudaGetSymbolAddress((void**)&vtl,   g_vt_l);

    cudaFuncSetAttribute(mma_gemm3,
                         cudaFuncAttributeMaxDynamicSharedMemorySize, MMA_SMEM3);
    cudaFuncSetAttribute(qkv_fused,
                         cudaFuncAttributeMaxDynamicSharedMemorySize, MMA_SMEM3);
    cudaFuncSetAttribute(flash_attn,
                         cudaFuncAttributeMaxDynamicSharedMemorySize, AT_SMEM);

    // 1) hi/lo splits of x and input-proj weights
    split2<<<(Mm * Ee) / 1024, 256>>>(x, A1h, A1l);
    split2<<<(QKVN * Ee) / 1024, 256>>>(Wl_in, B1lh, B1ll);
    split2<<<(QKVN * Ee) / 1024, 256>>>(Wg_in, B1gh, B1gl);

    // 2) combined epilogue weights + bias, then split
    wc_gemm<<<dim3(8, 8, 2), 256>>>(Wf, Wl_out, Wg_out, Wc);
    bias_combine_kernel<<<Ee, 128>>>(Wf, bl_out, bg_out, bf);
    split2<<<(Ee * 2 * Ee) / 1024, 256>>>(Wc, B2h, B2l);

    // 3) fused QKV projections
    qkv_fused<<<dim3(QKVN / 64, Mm / 128, 2), 128, MMA_SMEM3>>>(
        A1h, A1l, bl_in, bg_in);

    // 4) local attention -> A2
    local_attn_kernel<<<(Bb * Hh * Ss) / 8, 256>>>(qkv_l);

    // 5) V transpose-split, flash attention
    vt_split<<<dim3(Ss / 64, Bb * Hh), 256>>>(vg, vth, vtl);
    flash_attn<<<dim3(Ss / 64, Bb * Hh), 128, AT_SMEM>>>(qkh, qkl, vth, vtl);

    // 6) final fused projection + ReLU
    mma_gemm3<<<dim3(Ee / 64, Mm / 128), 128, MMA_SMEM3>>>(
        A2h, A2l, B2h, B2l, bc, out, 1024, Ee);
}